// round 2
// baseline (speedup 1.0000x reference)
#include <cuda_runtime.h>

// Problem constants
#define Bn   4
#define Cc   256
#define Nn   4096
#define Gg   32
#define CPG  8              // channels per group = 256/32
#define EPSf 1e-6f
#define SCALEf 0.0625f      // C^-0.5 = 1/16
#define RSQRT2f 0.70710678118654752440f

// Scratch (device globals — allocation-free contract).
// Layouts are all channel-major [B, C, N] except g_p which is [B, N, N].
__device__ float g_hs[Bn * Cc * Nn];           // groupnorm output
__device__ float g_q [Bn * Cc * Nn];
__device__ float g_k [Bn * Cc * Nn];
__device__ float g_v [Bn * Cc * Nn];
__device__ float g_p [(size_t)Bn * Nn * Nn];   // scores -> softmax probs (256 MB)
__device__ float g_ao[Bn * Cc * Nn];           // attention output (pre out-proj)

// ---------------------------------------------------------------------------
// GroupNorm: one block per (batch, group).
// ---------------------------------------------------------------------------
__global__ void __launch_bounds__(256) gn_kernel(const float* __restrict__ x,
                                                 const float* __restrict__ w,
                                                 const float* __restrict__ bgn) {
    const int bg = blockIdx.x;
    const int bb = bg >> 5;
    const int g  = bg & 31;
    const int GSIZE = CPG * Nn;    // 32768
    const size_t base = (size_t)(bb * Cc + g * CPG) * Nn;
    const float* xp = x + base;

    float s = 0.f, s2 = 0.f;
    for (int i = threadIdx.x; i < GSIZE; i += 256) {
        float v = xp[i];
        s += v; s2 += v * v;
    }
    __shared__ float r1[8], r2[8];
    __shared__ float sh_mean, sh_rstd;
    #pragma unroll
    for (int o = 16; o; o >>= 1) {
        s  += __shfl_xor_sync(0xffffffffu, s,  o);
        s2 += __shfl_xor_sync(0xffffffffu, s2, o);
    }
    if ((threadIdx.x & 31) == 0) { r1[threadIdx.x >> 5] = s; r2[threadIdx.x >> 5] = s2; }
    __syncthreads();
    if (threadIdx.x == 0) {
        s = 0.f; s2 = 0.f;
        #pragma unroll
        for (int i = 0; i < 8; i++) { s += r1[i]; s2 += r2[i]; }
        float mean = s * (1.f / GSIZE);
        float var  = s2 * (1.f / GSIZE) - mean * mean;
        sh_mean = mean;
        sh_rstd = rsqrtf(var + EPSf);
    }
    __syncthreads();
    const float mean = sh_mean, rstd = sh_rstd;
    for (int i = threadIdx.x; i < GSIZE; i += 256) {
        int c = g * CPG + (i >> 12);
        g_hs[base + i] = (xp[i] - mean) * rstd * w[c] + bgn[c];
    }
}

// ---------------------------------------------------------------------------
// GEMM NN: out[m][n] = sum_k A[m][k] * Bm[k][n] (+ bias[m]).  QKV projections.
// ---------------------------------------------------------------------------
__global__ void __launch_bounds__(256) qkv_kernel(const float* __restrict__ Wq,
                                                  const float* __restrict__ bq,
                                                  const float* __restrict__ Wk,
                                                  const float* __restrict__ bk,
                                                  const float* __restrict__ Wv,
                                                  const float* __restrict__ bv) {
    const int z  = blockIdx.z;     // 0..11
    const int which = z >> 2;
    const int bb    = z & 3;
    const float* A;  const float* bias;  float* Cm;
    if (which == 0)      { A = Wq; bias = bq; Cm = g_q; }
    else if (which == 1) { A = Wk; bias = bk; Cm = g_k; }
    else                 { A = Wv; bias = bv; Cm = g_v; }
    const float* Bm = g_hs + (size_t)bb * Cc * Nn;
    Cm += (size_t)bb * Cc * Nn;

    __shared__ float As[16][132];
    __shared__ float Bs[16][132];
    float acc[8][8];
    #pragma unroll
    for (int i = 0; i < 8; i++)
        #pragma unroll
        for (int j = 0; j < 8; j++) acc[i][j] = 0.f;

    const int tid = threadIdx.x;
    const int tx = tid & 15, ty = tid >> 4;
    const int rowBase = blockIdx.y * 128;
    const int colBase = blockIdx.x * 128;

    for (int k0 = 0; k0 < Cc; k0 += 16) {
        #pragma unroll
        for (int l = tid * 4; l < 2048; l += 1024) {
            int m  = l >> 4, kk = l & 15;
            float4 a4 = *(const float4*)(A + (size_t)(rowBase + m) * Cc + k0 + kk);
            As[kk + 0][m] = a4.x; As[kk + 1][m] = a4.y;
            As[kk + 2][m] = a4.z; As[kk + 3][m] = a4.w;
            int kb = l >> 7, j = l & 127;
            *(float4*)&Bs[kb][j] = *(const float4*)(Bm + (size_t)(k0 + kb) * Nn + colBase + j);
        }
        __syncthreads();
        #pragma unroll
        for (int kk = 0; kk < 16; kk++) {
            float ra[8], rb[8];
            *(float4*)(ra)     = *(float4*)&As[kk][ty * 8];
            *(float4*)(ra + 4) = *(float4*)&As[kk][ty * 8 + 4];
            *(float4*)(rb)     = *(float4*)&Bs[kk][tx * 8];
            *(float4*)(rb + 4) = *(float4*)&Bs[kk][tx * 8 + 4];
            #pragma unroll
            for (int i = 0; i < 8; i++)
                #pragma unroll
                for (int j = 0; j < 8; j++) acc[i][j] += ra[i] * rb[j];
        }
        __syncthreads();
    }
    #pragma unroll
    for (int i = 0; i < 8; i++) {
        int m = rowBase + ty * 8 + i;
        float bv_ = bias[m];
        float* op = Cm + (size_t)m * Nn + colBase + tx * 8;
        float4 v0, v1;
        v0.x = acc[i][0] + bv_; v0.y = acc[i][1] + bv_;
        v0.z = acc[i][2] + bv_; v0.w = acc[i][3] + bv_;
        v1.x = acc[i][4] + bv_; v1.y = acc[i][5] + bv_;
        v1.z = acc[i][6] + bv_; v1.w = acc[i][7] + bv_;
        *(float4*)(op)     = v0;
        *(float4*)(op + 4) = v1;
    }
}

// ---------------------------------------------------------------------------
// GEMM TN (double-buffered): S[i][j] = scale * sum_c Q[c][i] * K[c][j].
// ---------------------------------------------------------------------------
__global__ void __launch_bounds__(256) scores_kernel() {
    const int bb = blockIdx.z;
    const float* Q  = g_q + (size_t)bb * Cc * Nn;
    const float* Kt = g_k + (size_t)bb * Cc * Nn;
    float* S = g_p + (size_t)bb * Nn * Nn;

    __shared__ float As[2][16][132];
    __shared__ float Bs[2][16][132];
    float acc[8][8];
    #pragma unroll
    for (int i = 0; i < 8; i++)
        #pragma unroll
        for (int j = 0; j < 8; j++) acc[i][j] = 0.f;

    const int tid = threadIdx.x;
    const int tx = tid & 15, ty = tid >> 4;
    const int rowBase = blockIdx.y * 128;
    const int colBase = blockIdx.x * 128;

    // Each thread owns two float4 slots per operand tile.
    const int l0 = tid * 4,       l1 = tid * 4 + 1024;
    const int kkA = l0 >> 7, iiA = l0 & 127;
    const int kkB = l1 >> 7, iiB = l1 & 127;

    // Preload k0 = 0 into buffer 0.
    *(float4*)&As[0][kkA][iiA] = *(const float4*)(Q  + (size_t)kkA * Nn + rowBase + iiA);
    *(float4*)&Bs[0][kkA][iiA] = *(const float4*)(Kt + (size_t)kkA * Nn + colBase + iiA);
    *(float4*)&As[0][kkB][iiB] = *(const float4*)(Q  + (size_t)kkB * Nn + rowBase + iiB);
    *(float4*)&Bs[0][kkB][iiB] = *(const float4*)(Kt + (size_t)kkB * Nn + colBase + iiB);
    __syncthreads();

    int buf = 0;
    for (int k0 = 0; k0 < Cc; k0 += 16) {
        if (k0 + 16 < Cc) {
            const int nb = buf ^ 1, kn = k0 + 16;
            *(float4*)&As[nb][kkA][iiA] = *(const float4*)(Q  + (size_t)(kn + kkA) * Nn + rowBase + iiA);
            *(float4*)&Bs[nb][kkA][iiA] = *(const float4*)(Kt + (size_t)(kn + kkA) * Nn + colBase + iiA);
            *(float4*)&As[nb][kkB][iiB] = *(const float4*)(Q  + (size_t)(kn + kkB) * Nn + rowBase + iiB);
            *(float4*)&Bs[nb][kkB][iiB] = *(const float4*)(Kt + (size_t)(kn + kkB) * Nn + colBase + iiB);
        }
        #pragma unroll
        for (int kk = 0; kk < 16; kk++) {
            float ra[8], rb[8];
            *(float4*)(ra)     = *(float4*)&As[buf][kk][ty * 8];
            *(float4*)(ra + 4) = *(float4*)&As[buf][kk][ty * 8 + 4];
            *(float4*)(rb)     = *(float4*)&Bs[buf][kk][tx * 8];
            *(float4*)(rb + 4) = *(float4*)&Bs[buf][kk][tx * 8 + 4];
            #pragma unroll
            for (int i = 0; i < 8; i++)
                #pragma unroll
                for (int j = 0; j < 8; j++) acc[i][j] += ra[i] * rb[j];
        }
        __syncthreads();
        buf ^= 1;
    }
    #pragma unroll
    for (int i = 0; i < 8; i++) {
        float* op = S + (size_t)(rowBase + ty * 8 + i) * Nn + colBase + tx * 8;
        float4 v0, v1;
        v0.x = acc[i][0] * SCALEf; v0.y = acc[i][1] * SCALEf;
        v0.z = acc[i][2] * SCALEf; v0.w = acc[i][3] * SCALEf;
        v1.x = acc[i][4] * SCALEf; v1.y = acc[i][5] * SCALEf;
        v1.z = acc[i][6] * SCALEf; v1.w = acc[i][7] * SCALEf;
        *(float4*)(op)     = v0;
        *(float4*)(op + 4) = v1;
    }
}

// ---------------------------------------------------------------------------
// Row softmax over g_p: one block per row, row cached in smem.
// ---------------------------------------------------------------------------
__global__ void __launch_bounds__(256) softmax_kernel() {
    __shared__ float buf[Nn];
    __shared__ float red[8];
    float* p = g_p + (size_t)blockIdx.x * Nn;
    const int tid = threadIdx.x;

    float m = -3.4e38f;
    for (int i = tid; i < Nn; i += 256) { float v = p[i]; buf[i] = v; m = fmaxf(m, v); }
    #pragma unroll
    for (int o = 16; o; o >>= 1) m = fmaxf(m, __shfl_xor_sync(0xffffffffu, m, o));
    if ((tid & 31) == 0) red[tid >> 5] = m;
    __syncthreads();
    if (tid < 8) {
        m = red[tid];
        #pragma unroll
        for (int o = 4; o; o >>= 1) m = fmaxf(m, __shfl_xor_sync(0xffu, m, o));
        if (tid == 0) red[0] = m;
    }
    __syncthreads();
    m = red[0];
    __syncthreads();

    float sum = 0.f;
    for (int i = tid; i < Nn; i += 256) { float e = __expf(buf[i] - m); buf[i] = e; sum += e; }
    #pragma unroll
    for (int o = 16; o; o >>= 1) sum += __shfl_xor_sync(0xffffffffu, sum, o);
    if ((tid & 31) == 0) red[tid >> 5] = sum;
    __syncthreads();
    if (tid < 8) {
        sum = red[tid];
        #pragma unroll
        for (int o = 4; o; o >>= 1) sum += __shfl_xor_sync(0xffu, sum, o);
        if (tid == 0) red[0] = sum;
    }
    __syncthreads();
    const float inv = 1.f / red[0];
    for (int i = tid; i < Nn; i += 256) p[i] = buf[i] * inv;
}

// ---------------------------------------------------------------------------
// GEMM NT (double-buffered): AO[c][n] = sum_j V[c][j] * P[n][j].
// ---------------------------------------------------------------------------
__global__ void __launch_bounds__(256) ao_kernel() {
    const int bb = blockIdx.z;
    const float* Vp = g_v + (size_t)bb * Cc * Nn;
    const float* Pp = g_p + (size_t)bb * Nn * Nn;
    float* AO = g_ao + (size_t)bb * Cc * Nn;

    __shared__ float As[2][16][132];
    __shared__ float Bs[2][16][132];
    float acc[8][8];
    #pragma unroll
    for (int i = 0; i < 8; i++)
        #pragma unroll
        for (int j = 0; j < 8; j++) acc[i][j] = 0.f;

    const int tid = threadIdx.x;
    const int tx = tid & 15, ty = tid >> 4;
    const int rowBase = blockIdx.y * 128;   // c
    const int colBase = blockIdx.x * 128;   // n

    // Two transpose-scatter slots per thread per operand.
    const int l0 = tid * 4,        l1 = tid * 4 + 1024;
    const int m0 = l0 >> 4, kk0 = l0 & 15;
    const int m1 = l1 >> 4, kk1 = l1 & 15;

    // Preload k0 = 0 into buffer 0.
    {
        float4 a0 = *(const float4*)(Vp + (size_t)(rowBase + m0) * Nn + kk0);
        As[0][kk0 + 0][m0] = a0.x; As[0][kk0 + 1][m0] = a0.y;
        As[0][kk0 + 2][m0] = a0.z; As[0][kk0 + 3][m0] = a0.w;
        float4 b0 = *(const float4*)(Pp + (size_t)(colBase + m0) * Nn + kk0);
        Bs[0][kk0 + 0][m0] = b0.x; Bs[0][kk0 + 1][m0] = b0.y;
        Bs[0][kk0 + 2][m0] = b0.z; Bs[0][kk0 + 3][m0] = b0.w;
        float4 a1 = *(const float4*)(Vp + (size_t)(rowBase + m1) * Nn + kk1);
        As[0][kk1 + 0][m1] = a1.x; As[0][kk1 + 1][m1] = a1.y;
        As[0][kk1 + 2][m1] = a1.z; As[0][kk1 + 3][m1] = a1.w;
        float4 b1 = *(const float4*)(Pp + (size_t)(colBase + m1) * Nn + kk1);
        Bs[0][kk1 + 0][m1] = b1.x; Bs[0][kk1 + 1][m1] = b1.y;
        Bs[0][kk1 + 2][m1] = b1.z; Bs[0][kk1 + 3][m1] = b1.w;
    }
    __syncthreads();

    int buf = 0;
    for (int k0 = 0; k0 < Nn; k0 += 16) {
        if (k0 + 16 < Nn) {
            const int nb = buf ^ 1, kn = k0 + 16;
            float4 a0 = *(const float4*)(Vp + (size_t)(rowBase + m0) * Nn + kn + kk0);
            As[nb][kk0 + 0][m0] = a0.x; As[nb][kk0 + 1][m0] = a0.y;
            As[nb][kk0 + 2][m0] = a0.z; As[nb][kk0 + 3][m0] = a0.w;
            float4 b0 = *(const float4*)(Pp + (size_t)(colBase + m0) * Nn + kn + kk0);
            Bs[nb][kk0 + 0][m0] = b0.x; Bs[nb][kk0 + 1][m0] = b0.y;
            Bs[nb][kk0 + 2][m0] = b0.z; Bs[nb][kk0 + 3][m0] = b0.w;
            float4 a1 = *(const float4*)(Vp + (size_t)(rowBase + m1) * Nn + kn + kk1);
            As[nb][kk1 + 0][m1] = a1.x; As[nb][kk1 + 1][m1] = a1.y;
            As[nb][kk1 + 2][m1] = a1.z; As[nb][kk1 + 3][m1] = a1.w;
            float4 b1 = *(const float4*)(Pp + (size_t)(colBase + m1) * Nn + kn + kk1);
            Bs[nb][kk1 + 0][m1] = b1.x; Bs[nb][kk1 + 1][m1] = b1.y;
            Bs[nb][kk1 + 2][m1] = b1.z; Bs[nb][kk1 + 3][m1] = b1.w;
        }
        #pragma unroll
        for (int kk = 0; kk < 16; kk++) {
            float ra[8], rb[8];
            *(float4*)(ra)     = *(float4*)&As[buf][kk][ty * 8];
            *(float4*)(ra + 4) = *(float4*)&As[buf][kk][ty * 8 + 4];
            *(float4*)(rb)     = *(float4*)&Bs[buf][kk][tx * 8];
            *(float4*)(rb + 4) = *(float4*)&Bs[buf][kk][tx * 8 + 4];
            #pragma unroll
            for (int i = 0; i < 8; i++)
                #pragma unroll
                for (int j = 0; j < 8; j++) acc[i][j] += ra[i] * rb[j];
        }
        __syncthreads();
        buf ^= 1;
    }
    #pragma unroll
    for (int i = 0; i < 8; i++) {
        float* op = AO + (size_t)(rowBase + ty * 8 + i) * Nn + colBase + tx * 8;
        *(float4*)(op)     = *(float4*)&acc[i][0];
        *(float4*)(op + 4) = *(float4*)&acc[i][4];
    }
}

// ---------------------------------------------------------------------------
// Output projection (NN) + residual epilogue.
// ---------------------------------------------------------------------------
__global__ void __launch_bounds__(256) outproj_kernel(const float* __restrict__ Wo,
                                                      const float* __restrict__ bo,
                                                      const float* __restrict__ x,
                                                      float* __restrict__ out) {
    const int bb = blockIdx.z;
    const float* Bm = g_ao + (size_t)bb * Cc * Nn;

    __shared__ float As[16][132];
    __shared__ float Bs[16][132];
    float acc[8][8];
    #pragma unroll
    for (int i = 0; i < 8; i++)
        #pragma unroll
        for (int j = 0; j < 8; j++) acc[i][j] = 0.f;

    const int tid = threadIdx.x;
    const int tx = tid & 15, ty = tid >> 4;
    const int rowBase = blockIdx.y * 128;
    const int colBase = blockIdx.x * 128;

    for (int k0 = 0; k0 < Cc; k0 += 16) {
        #pragma unroll
        for (int l = tid * 4; l < 2048; l += 1024) {
            int m  = l >> 4, kk = l & 15;
            float4 a4 = *(const float4*)(Wo + (size_t)(rowBase + m) * Cc + k0 + kk);
            As[kk + 0][m] = a4.x; As[kk + 1][m] = a4.y;
            As[kk + 2][m] = a4.z; As[kk + 3][m] = a4.w;
            int kb = l >> 7, j = l & 127;
            *(float4*)&Bs[kb][j] = *(const float4*)(Bm + (size_t)(k0 + kb) * Nn + colBase + j);
        }
        __syncthreads();
        #pragma unroll
        for (int kk = 0; kk < 16; kk++) {
            float ra[8], rb[8];
            *(float4*)(ra)     = *(float4*)&As[kk][ty * 8];
            *(float4*)(ra + 4) = *(float4*)&As[kk][ty * 8 + 4];
            *(float4*)(rb)     = *(float4*)&Bs[kk][tx * 8];
            *(float4*)(rb + 4) = *(float4*)&Bs[kk][tx * 8 + 4];
            #pragma unroll
            for (int i = 0; i < 8; i++)
                #pragma unroll
                for (int j = 0; j < 8; j++) acc[i][j] += ra[i] * rb[j];
        }
        __syncthreads();
    }
    #pragma unroll
    for (int i = 0; i < 8; i++) {
        int m = rowBase + ty * 8 + i;
        float bv_ = bo[m];
        size_t idx = (size_t)(bb * Cc + m) * Nn + colBase + tx * 8;
        const float* xp = x + idx;
        float* op = out + idx;
        float4 x0 = *(const float4*)(xp);
        float4 x1 = *(const float4*)(xp + 4);
        float4 v0, v1;
        v0.x = (x0.x + acc[i][0] + bv_) * RSQRT2f;
        v0.y = (x0.y + acc[i][1] + bv_) * RSQRT2f;
        v0.z = (x0.z + acc[i][2] + bv_) * RSQRT2f;
        v0.w = (x0.w + acc[i][3] + bv_) * RSQRT2f;
        v1.x = (x1.x + acc[i][4] + bv_) * RSQRT2f;
        v1.y = (x1.y + acc[i][5] + bv_) * RSQRT2f;
        v1.z = (x1.z + acc[i][6] + bv_) * RSQRT2f;
        v1.w = (x1.w + acc[i][7] + bv_) * RSQRT2f;
        *(float4*)(op)     = v0;
        *(float4*)(op + 4) = v1;
    }
}

// ---------------------------------------------------------------------------
extern "C" void kernel_launch(void* const* d_in, const int* in_sizes, int n_in,
                              void* d_out, int out_size) {
    const float* x  = (const float*)d_in[0];
    const float* gw = (const float*)d_in[1];
    const float* gb = (const float*)d_in[2];
    const float* Wq = (const float*)d_in[3];
    const float* bq = (const float*)d_in[4];
    const float* Wk = (const float*)d_in[5];
    const float* bk = (const float*)d_in[6];
    const float* Wv = (const float*)d_in[7];
    const float* bv = (const float*)d_in[8];
    const float* Wo = (const float*)d_in[9];
    const float* bo = (const float*)d_in[10];
    float* out = (float*)d_out;

    gn_kernel<<<Bn * Gg, 256>>>(x, gw, gb);
    qkv_kernel<<<dim3(Nn / 128, Cc / 128, 12), 256>>>(Wq, bq, Wk, bk, Wv, bv);
    scores_kernel<<<dim3(Nn / 128, Nn / 128, Bn), 256>>>();
    softmax_kernel<<<Bn * Nn, 256>>>();
    ao_kernel<<<dim3(Nn / 128, Cc / 128, Bn), 256>>>();
    outproj_kernel<<<dim3(Nn / 128, Cc / 128, Bn), 256>>>(Wo, bo, x, out);
}

// round 3
// speedup vs baseline: 2.0370x; 2.0370x over previous
#include <cuda_runtime.h>

// Problem constants
#define Bn   4
#define Cc   256
#define Nn   4096
#define Gg   32
#define CPG  8
#define EPSf 1e-6f
#define SCALEf 0.0625f
#define RSQRT2f 0.70710678118654752440f

#define PITCH 136   // smem row pitch (floats); 136 % 32 == 8 -> conflict-free fragment LDS

// Scratch (device globals — allocation-free contract).
__device__ float g_hs[Bn * Cc * Nn];
__device__ float g_q [Bn * Cc * Nn];
__device__ float g_k [Bn * Cc * Nn];
__device__ float g_v [Bn * Cc * Nn];
__device__ float g_p [(size_t)Bn * Nn * Nn];
__device__ float g_ao[Bn * Cc * Nn];

__device__ __forceinline__ float cvt_tf32(float x) {
    unsigned u;
    asm("cvt.rna.tf32.f32 %0, %1;" : "=r"(u) : "f"(x));
    return __uint_as_float(u);
}
__device__ __forceinline__ float4 cvt_tf32_4(float4 v) {
    float4 r;
    r.x = cvt_tf32(v.x); r.y = cvt_tf32(v.y);
    r.z = cvt_tf32(v.z); r.w = cvt_tf32(v.w);
    return r;
}

// One m16n8k8 tf32 mma: acc (4 floats) += A(4regs) * B(2regs)
#define MMA_TF32(ac, a0, a1, a2, a3, b0, b1)                                   \
    asm volatile("mma.sync.aligned.m16n8k8.row.col.f32.tf32.tf32.f32 "         \
                 "{%0,%1,%2,%3}, {%4,%5,%6,%7}, {%8,%9}, {%0,%1,%2,%3};"       \
                 : "+f"(ac[0]), "+f"(ac[1]), "+f"(ac[2]), "+f"(ac[3])          \
                 : "r"(a0), "r"(a1), "r"(a2), "r"(a3), "r"(b0), "r"(b1))

// Fragment load + 16 mma for one k8 slice from As[16][PITCH], Bs[16][PITCH].
// mW: warp m offset (0..96), nW: warp n offset (0/64), lr=lane/4, lc=lane%4.
#define MMA_K8(As_, Bs_, kk)                                                   \
    {                                                                          \
        unsigned a[2][4], b[8][2];                                             \
        _Pragma("unroll")                                                      \
        for (int ma = 0; ma < 2; ma++) {                                       \
            int m0 = mW + ma * 16 + lr;                                        \
            a[ma][0] = __float_as_uint(As_[(kk) + lc    ][m0]);                \
            a[ma][1] = __float_as_uint(As_[(kk) + lc    ][m0 + 8]);            \
            a[ma][2] = __float_as_uint(As_[(kk) + lc + 4][m0]);                \
            a[ma][3] = __float_as_uint(As_[(kk) + lc + 4][m0 + 8]);            \
        }                                                                      \
        _Pragma("unroll")                                                      \
        for (int na = 0; na < 8; na++) {                                       \
            int n0 = nW + na * 8 + lr;                                         \
            b[na][0] = __float_as_uint(Bs_[(kk) + lc    ][n0]);                \
            b[na][1] = __float_as_uint(Bs_[(kk) + lc + 4][n0]);                \
        }                                                                      \
        _Pragma("unroll")                                                      \
        for (int ma = 0; ma < 2; ma++)                                         \
            _Pragma("unroll")                                                  \
            for (int na = 0; na < 8; na++)                                     \
                MMA_TF32(acc[ma][na], a[ma][0], a[ma][1], a[ma][2], a[ma][3],  \
                         b[na][0], b[na][1]);                                  \
    }

// ---------------------------------------------------------------------------
// GroupNorm
// ---------------------------------------------------------------------------
__global__ void __launch_bounds__(256) gn_kernel(const float* __restrict__ x,
                                                 const float* __restrict__ w,
                                                 const float* __restrict__ bgn) {
    const int bg = blockIdx.x;
    const int bb = bg >> 5;
    const int g  = bg & 31;
    const int GSIZE = CPG * Nn;
    const size_t base = (size_t)(bb * Cc + g * CPG) * Nn;
    const float* xp = x + base;

    float s = 0.f, s2 = 0.f;
    for (int i = threadIdx.x; i < GSIZE; i += 256) {
        float v = xp[i];
        s += v; s2 += v * v;
    }
    __shared__ float r1[8], r2[8];
    __shared__ float sh_mean, sh_rstd;
    #pragma unroll
    for (int o = 16; o; o >>= 1) {
        s  += __shfl_xor_sync(0xffffffffu, s,  o);
        s2 += __shfl_xor_sync(0xffffffffu, s2, o);
    }
    if ((threadIdx.x & 31) == 0) { r1[threadIdx.x >> 5] = s; r2[threadIdx.x >> 5] = s2; }
    __syncthreads();
    if (threadIdx.x == 0) {
        s = 0.f; s2 = 0.f;
        #pragma unroll
        for (int i = 0; i < 8; i++) { s += r1[i]; s2 += r2[i]; }
        float mean = s * (1.f / GSIZE);
        float var  = s2 * (1.f / GSIZE) - mean * mean;
        sh_mean = mean;
        sh_rstd = rsqrtf(var + EPSf);
    }
    __syncthreads();
    const float mean = sh_mean, rstd = sh_rstd;
    for (int i = threadIdx.x; i < GSIZE; i += 256) {
        int c = g * CPG + (i >> 12);
        g_hs[base + i] = (xp[i] - mean) * rstd * w[c] + bgn[c];
    }
}

// ---------------------------------------------------------------------------
// QKV projections (NN, tf32 mma): out[m][n] = sum_k W[m][k]*hs[k][n] + b[m]
// ---------------------------------------------------------------------------
__global__ void __launch_bounds__(256, 2) qkv_kernel(const float* __restrict__ Wq,
                                                     const float* __restrict__ bq,
                                                     const float* __restrict__ Wk,
                                                     const float* __restrict__ bk,
                                                     const float* __restrict__ Wv,
                                                     const float* __restrict__ bv) {
    const int z  = blockIdx.z;
    const int which = z >> 2;
    const int bb    = z & 3;
    const float* A;  const float* bias;  float* Cm;
    if (which == 0)      { A = Wq; bias = bq; Cm = g_q; }
    else if (which == 1) { A = Wk; bias = bk; Cm = g_k; }
    else                 { A = Wv; bias = bv; Cm = g_v; }
    const float* Bm = g_hs + (size_t)bb * Cc * Nn;
    Cm += (size_t)bb * Cc * Nn;

    __shared__ float As[16][PITCH];
    __shared__ float Bs[16][PITCH];
    float acc[2][8][4];
    #pragma unroll
    for (int i = 0; i < 2; i++)
        #pragma unroll
        for (int j = 0; j < 8; j++)
            #pragma unroll
            for (int r = 0; r < 4; r++) acc[i][j][r] = 0.f;

    const int tid = threadIdx.x;
    const int lane = tid & 31, wid = tid >> 5;
    const int lr = lane >> 2, lc = lane & 3;
    const int mW = (wid & 3) * 32, nW = (wid >> 2) * 64;
    const int rowBase = blockIdx.y * 128;
    const int colBase = blockIdx.x * 128;

    for (int k0 = 0; k0 < Cc; k0 += 16) {
        #pragma unroll
        for (int l = tid * 4; l < 2048; l += 1024) {
            int m  = l >> 4, kk = l & 15;
            float4 a4 = cvt_tf32_4(*(const float4*)(A + (size_t)(rowBase + m) * Cc + k0 + kk));
            As[kk + 0][m] = a4.x; As[kk + 1][m] = a4.y;
            As[kk + 2][m] = a4.z; As[kk + 3][m] = a4.w;
            int kb = l >> 7, j = l & 127;
            *(float4*)&Bs[kb][j] =
                cvt_tf32_4(*(const float4*)(Bm + (size_t)(k0 + kb) * Nn + colBase + j));
        }
        __syncthreads();
        MMA_K8(As, Bs, 0)
        MMA_K8(As, Bs, 8)
        __syncthreads();
    }
    #pragma unroll
    for (int ma = 0; ma < 2; ma++) {
        int m0 = rowBase + mW + ma * 16 + lr;
        float b0 = bias[m0], b1 = bias[m0 + 8];
        #pragma unroll
        for (int na = 0; na < 8; na++) {
            int cI = colBase + nW + na * 8 + 2 * lc;
            float2 v0 = {acc[ma][na][0] + b0, acc[ma][na][1] + b0};
            float2 v1 = {acc[ma][na][2] + b1, acc[ma][na][3] + b1};
            *(float2*)(Cm + (size_t)m0 * Nn + cI)       = v0;
            *(float2*)(Cm + (size_t)(m0 + 8) * Nn + cI) = v1;
        }
    }
}

// ---------------------------------------------------------------------------
// Scores (TN, tf32 mma, double-buffered): S = scale * Q^T K
// ---------------------------------------------------------------------------
__global__ void __launch_bounds__(256, 2) scores_kernel() {
    const int bb = blockIdx.z;
    const float* Q  = g_q + (size_t)bb * Cc * Nn;
    const float* Kt = g_k + (size_t)bb * Cc * Nn;
    float* S = g_p + (size_t)bb * Nn * Nn;

    __shared__ float As[2][16][PITCH];
    __shared__ float Bs[2][16][PITCH];
    float acc[2][8][4];
    #pragma unroll
    for (int i = 0; i < 2; i++)
        #pragma unroll
        for (int j = 0; j < 8; j++)
            #pragma unroll
            for (int r = 0; r < 4; r++) acc[i][j][r] = 0.f;

    const int tid = threadIdx.x;
    const int lane = tid & 31, wid = tid >> 5;
    const int lr = lane >> 2, lc = lane & 3;
    const int mW = (wid & 3) * 32, nW = (wid >> 2) * 64;
    const int rowBase = blockIdx.y * 128;
    const int colBase = blockIdx.x * 128;

    const int l0 = tid * 4,       l1 = tid * 4 + 1024;
    const int kkA = l0 >> 7, iiA = l0 & 127;
    const int kkB = l1 >> 7, iiB = l1 & 127;

    *(float4*)&As[0][kkA][iiA] = cvt_tf32_4(*(const float4*)(Q  + (size_t)kkA * Nn + rowBase + iiA));
    *(float4*)&Bs[0][kkA][iiA] = cvt_tf32_4(*(const float4*)(Kt + (size_t)kkA * Nn + colBase + iiA));
    *(float4*)&As[0][kkB][iiB] = cvt_tf32_4(*(const float4*)(Q  + (size_t)kkB * Nn + rowBase + iiB));
    *(float4*)&Bs[0][kkB][iiB] = cvt_tf32_4(*(const float4*)(Kt + (size_t)kkB * Nn + colBase + iiB));
    __syncthreads();

    int buf = 0;
    for (int k0 = 0; k0 < Cc; k0 += 16) {
        if (k0 + 16 < Cc) {
            const int nb = buf ^ 1, kn = k0 + 16;
            *(float4*)&As[nb][kkA][iiA] = cvt_tf32_4(*(const float4*)(Q  + (size_t)(kn + kkA) * Nn + rowBase + iiA));
            *(float4*)&Bs[nb][kkA][iiA] = cvt_tf32_4(*(const float4*)(Kt + (size_t)(kn + kkA) * Nn + colBase + iiA));
            *(float4*)&As[nb][kkB][iiB] = cvt_tf32_4(*(const float4*)(Q  + (size_t)(kn + kkB) * Nn + rowBase + iiB));
            *(float4*)&Bs[nb][kkB][iiB] = cvt_tf32_4(*(const float4*)(Kt + (size_t)(kn + kkB) * Nn + colBase + iiB));
        }
        MMA_K8(As[buf], Bs[buf], 0)
        MMA_K8(As[buf], Bs[buf], 8)
        __syncthreads();
        buf ^= 1;
    }
    #pragma unroll
    for (int ma = 0; ma < 2; ma++) {
        int m0 = rowBase + mW + ma * 16 + lr;
        #pragma unroll
        for (int na = 0; na < 8; na++) {
            int cI = colBase + nW + na * 8 + 2 * lc;
            float2 v0 = {acc[ma][na][0] * SCALEf, acc[ma][na][1] * SCALEf};
            float2 v1 = {acc[ma][na][2] * SCALEf, acc[ma][na][3] * SCALEf};
            *(float2*)(S + (size_t)m0 * Nn + cI)       = v0;
            *(float2*)(S + (size_t)(m0 + 8) * Nn + cI) = v1;
        }
    }
}

// ---------------------------------------------------------------------------
// Row softmax
// ---------------------------------------------------------------------------
__global__ void __launch_bounds__(256) softmax_kernel() {
    __shared__ float buf[Nn];
    __shared__ float red[8];
    float* p = g_p + (size_t)blockIdx.x * Nn;
    const int tid = threadIdx.x;

    float m = -3.4e38f;
    for (int i = tid; i < Nn; i += 256) { float v = p[i]; buf[i] = v; m = fmaxf(m, v); }
    #pragma unroll
    for (int o = 16; o; o >>= 1) m = fmaxf(m, __shfl_xor_sync(0xffffffffu, m, o));
    if ((tid & 31) == 0) red[tid >> 5] = m;
    __syncthreads();
    if (tid < 8) {
        m = red[tid];
        #pragma unroll
        for (int o = 4; o; o >>= 1) m = fmaxf(m, __shfl_xor_sync(0xffu, m, o));
        if (tid == 0) red[0] = m;
    }
    __syncthreads();
    m = red[0];
    __syncthreads();

    float sum = 0.f;
    for (int i = tid; i < Nn; i += 256) { float e = __expf(buf[i] - m); buf[i] = e; sum += e; }
    #pragma unroll
    for (int o = 16; o; o >>= 1) sum += __shfl_xor_sync(0xffffffffu, sum, o);
    if ((tid & 31) == 0) red[tid >> 5] = sum;
    __syncthreads();
    if (tid < 8) {
        sum = red[tid];
        #pragma unroll
        for (int o = 4; o; o >>= 1) sum += __shfl_xor_sync(0xffu, sum, o);
        if (tid == 0) red[0] = sum;
    }
    __syncthreads();
    const float inv = 1.f / red[0];
    for (int i = tid; i < Nn; i += 256) p[i] = buf[i] * inv;
}

// ---------------------------------------------------------------------------
// AO (NT, tf32 mma, double-buffered): AO[c][n] = sum_j V[c][j] * P[n][j]
// ---------------------------------------------------------------------------
__global__ void __launch_bounds__(256, 2) ao_kernel() {
    const int bb = blockIdx.z;
    const float* Vp = g_v + (size_t)bb * Cc * Nn;
    const float* Pp = g_p + (size_t)bb * Nn * Nn;
    float* AO = g_ao + (size_t)bb * Cc * Nn;

    __shared__ float As[2][16][PITCH];
    __shared__ float Bs[2][16][PITCH];
    float acc[2][8][4];
    #pragma unroll
    for (int i = 0; i < 2; i++)
        #pragma unroll
        for (int j = 0; j < 8; j++)
            #pragma unroll
            for (int r = 0; r < 4; r++) acc[i][j][r] = 0.f;

    const int tid = threadIdx.x;
    const int lane = tid & 31, wid = tid >> 5;
    const int lr = lane >> 2, lc = lane & 3;
    const int mW = (wid & 3) * 32, nW = (wid >> 2) * 64;
    const int rowBase = blockIdx.y * 128;   // c
    const int colBase = blockIdx.x * 128;   // n

    const int l0 = tid * 4,        l1 = tid * 4 + 1024;
    const int m0i = l0 >> 4, kk0 = l0 & 15;
    const int m1i = l1 >> 4, kk1 = l1 & 15;

    {
        float4 a0 = cvt_tf32_4(*(const float4*)(Vp + (size_t)(rowBase + m0i) * Nn + kk0));
        As[0][kk0 + 0][m0i] = a0.x; As[0][kk0 + 1][m0i] = a0.y;
        As[0][kk0 + 2][m0i] = a0.z; As[0][kk0 + 3][m0i] = a0.w;
        float4 b0 = cvt_tf32_4(*(const float4*)(Pp + (size_t)(colBase + m0i) * Nn + kk0));
        Bs[0][kk0 + 0][m0i] = b0.x; Bs[0][kk0 + 1][m0i] = b0.y;
        Bs[0][kk0 + 2][m0i] = b0.z; Bs[0][kk0 + 3][m0i] = b0.w;
        float4 a1 = cvt_tf32_4(*(const float4*)(Vp + (size_t)(rowBase + m1i) * Nn + kk1));
        As[0][kk1 + 0][m1i] = a1.x; As[0][kk1 + 1][m1i] = a1.y;
        As[0][kk1 + 2][m1i] = a1.z; As[0][kk1 + 3][m1i] = a1.w;
        float4 b1 = cvt_tf32_4(*(const float4*)(Pp + (size_t)(colBase + m1i) * Nn + kk1));
        Bs[0][kk1 + 0][m1i] = b1.x; Bs[0][kk1 + 1][m1i] = b1.y;
        Bs[0][kk1 + 2][m1i] = b1.z; Bs[0][kk1 + 3][m1i] = b1.w;
    }
    __syncthreads();

    int buf = 0;
    for (int k0 = 0; k0 < Nn; k0 += 16) {
        if (k0 + 16 < Nn) {
            const int nb = buf ^ 1, kn = k0 + 16;
            float4 a0 = cvt_tf32_4(*(const float4*)(Vp + (size_t)(rowBase + m0i) * Nn + kn + kk0));
            As[nb][kk0 + 0][m0i] = a0.x; As[nb][kk0 + 1][m0i] = a0.y;
            As[nb][kk0 + 2][m0i] = a0.z; As[nb][kk0 + 3][m0i] = a0.w;
            float4 b0 = cvt_tf32_4(*(const float4*)(Pp + (size_t)(colBase + m0i) * Nn + kn + kk0));
            Bs[nb][kk0 + 0][m0i] = b0.x; Bs[nb][kk0 + 1][m0i] = b0.y;
            Bs[nb][kk0 + 2][m0i] = b0.z; Bs[nb][kk0 + 3][m0i] = b0.w;
            float4 a1 = cvt_tf32_4(*(const float4*)(Vp + (size_t)(rowBase + m1i) * Nn + kn + kk1));
            As[nb][kk1 + 0][m1i] = a1.x; As[nb][kk1 + 1][m1i] = a1.y;
            As[nb][kk1 + 2][m1i] = a1.z; As[nb][kk1 + 3][m1i] = a1.w;
            float4 b1 = cvt_tf32_4(*(const float4*)(Pp + (size_t)(colBase + m1i) * Nn + kn + kk1));
            Bs[nb][kk1 + 0][m1i] = b1.x; Bs[nb][kk1 + 1][m1i] = b1.y;
            Bs[nb][kk1 + 2][m1i] = b1.z; Bs[nb][kk1 + 3][m1i] = b1.w;
        }
        MMA_K8(As[buf], Bs[buf], 0)
        MMA_K8(As[buf], Bs[buf], 8)
        __syncthreads();
        buf ^= 1;
    }
    #pragma unroll
    for (int ma = 0; ma < 2; ma++) {
        int m0 = rowBase + mW + ma * 16 + lr;
        #pragma unroll
        for (int na = 0; na < 8; na++) {
            int cI = colBase + nW + na * 8 + 2 * lc;
            float2 v0 = {acc[ma][na][0], acc[ma][na][1]};
            float2 v1 = {acc[ma][na][2], acc[ma][na][3]};
            *(float2*)(AO + (size_t)m0 * Nn + cI)       = v0;
            *(float2*)(AO + (size_t)(m0 + 8) * Nn + cI) = v1;
        }
    }
}

// ---------------------------------------------------------------------------
// Output projection (NN, tf32 mma) + residual epilogue
// ---------------------------------------------------------------------------
__global__ void __launch_bounds__(256, 2) outproj_kernel(const float* __restrict__ Wo,
                                                         const float* __restrict__ bo,
                                                         const float* __restrict__ x,
                                                         float* __restrict__ out) {
    const int bb = blockIdx.z;
    const float* Bm = g_ao + (size_t)bb * Cc * Nn;

    __shared__ float As[16][PITCH];
    __shared__ float Bs[16][PITCH];
    float acc[2][8][4];
    #pragma unroll
    for (int i = 0; i < 2; i++)
        #pragma unroll
        for (int j = 0; j < 8; j++)
            #pragma unroll
            for (int r = 0; r < 4; r++) acc[i][j][r] = 0.f;

    const int tid = threadIdx.x;
    const int lane = tid & 31, wid = tid >> 5;
    const int lr = lane >> 2, lc = lane & 3;
    const int mW = (wid & 3) * 32, nW = (wid >> 2) * 64;
    const int rowBase = blockIdx.y * 128;
    const int colBase = blockIdx.x * 128;

    for (int k0 = 0; k0 < Cc; k0 += 16) {
        #pragma unroll
        for (int l = tid * 4; l < 2048; l += 1024) {
            int m  = l >> 4, kk = l & 15;
            float4 a4 = cvt_tf32_4(*(const float4*)(Wo + (size_t)(rowBase + m) * Cc + k0 + kk));
            As[kk + 0][m] = a4.x; As[kk + 1][m] = a4.y;
            As[kk + 2][m] = a4.z; As[kk + 3][m] = a4.w;
            int kb = l >> 7, j = l & 127;
            *(float4*)&Bs[kb][j] =
                cvt_tf32_4(*(const float4*)(Bm + (size_t)(k0 + kb) * Nn + colBase + j));
        }
        __syncthreads();
        MMA_K8(As, Bs, 0)
        MMA_K8(As, Bs, 8)
        __syncthreads();
    }
    #pragma unroll
    for (int ma = 0; ma < 2; ma++) {
        int m0 = rowBase + mW + ma * 16 + lr;
        float b0 = bo[m0], b1 = bo[m0 + 8];
        #pragma unroll
        for (int na = 0; na < 8; na++) {
            int cI = colBase + nW + na * 8 + 2 * lc;
            size_t i0 = (size_t)(bb * Cc + m0) * Nn + cI;
            size_t i1 = (size_t)(bb * Cc + m0 + 8) * Nn + cI;
            float2 x0 = *(const float2*)(x + i0);
            float2 x1 = *(const float2*)(x + i1);
            float2 v0 = {(x0.x + acc[ma][na][0] + b0) * RSQRT2f,
                         (x0.y + acc[ma][na][1] + b0) * RSQRT2f};
            float2 v1 = {(x1.x + acc[ma][na][2] + b1) * RSQRT2f,
                         (x1.y + acc[ma][na][3] + b1) * RSQRT2f};
            *(float2*)(out + i0) = v0;
            *(float2*)(out + i1) = v1;
        }
    }
}

// ---------------------------------------------------------------------------
extern "C" void kernel_launch(void* const* d_in, const int* in_sizes, int n_in,
                              void* d_out, int out_size) {
    const float* x  = (const float*)d_in[0];
    const float* gw = (const float*)d_in[1];
    const float* gb = (const float*)d_in[2];
    const float* Wq = (const float*)d_in[3];
    const float* bq = (const float*)d_in[4];
    const float* Wk = (const float*)d_in[5];
    const float* bk = (const float*)d_in[6];
    const float* Wv = (const float*)d_in[7];
    const float* bv = (const float*)d_in[8];
    const float* Wo = (const float*)d_in[9];
    const float* bo = (const float*)d_in[10];
    float* out = (float*)d_out;

    gn_kernel<<<Bn * Gg, 256>>>(x, gw, gb);
    qkv_kernel<<<dim3(Nn / 128, Cc / 128, 12), 256>>>(Wq, bq, Wk, bk, Wv, bv);
    scores_kernel<<<dim3(Nn / 128, Nn / 128, Bn), 256>>>();
    softmax_kernel<<<Bn * Nn, 256>>>();
    ao_kernel<<<dim3(Nn / 128, Cc / 128, Bn), 256>>>();
    outproj_kernel<<<dim3(Nn / 128, Cc / 128, Bn), 256>>>(Wo, bo, x, out);
}

// round 4
// speedup vs baseline: 2.0412x; 1.0021x over previous
#include <cuda_runtime.h>

// Problem constants
#define Bn   4
#define Cc   256
#define Nn   4096
#define Gg   32
#define CPG  8
#define EPSf 1e-6f
#define SCALEf 0.0625f
#define RSQRT2f 0.70710678118654752440f

#define PITCH 136   // smem row pitch (floats); 136 % 32 == 8 -> conflict-free fragment LDS

// Scratch (device globals — allocation-free contract).
__device__ float g_hs[Bn * Cc * Nn];
__device__ float g_q [Bn * Cc * Nn];
__device__ float g_k [Bn * Cc * Nn];
__device__ float g_v [Bn * Cc * Nn];
__device__ float g_p [(size_t)Bn * Nn * Nn];
__device__ float g_ao[Bn * Cc * Nn];

__device__ __forceinline__ float cvt_tf32(float x) {
    unsigned u;
    asm("cvt.rna.tf32.f32 %0, %1;" : "=r"(u) : "f"(x));
    return __uint_as_float(u);
}
__device__ __forceinline__ float4 cvt_tf32_4(float4 v) {
    float4 r;
    r.x = cvt_tf32(v.x); r.y = cvt_tf32(v.y);
    r.z = cvt_tf32(v.z); r.w = cvt_tf32(v.w);
    return r;
}

// One m16n8k8 tf32 mma: acc (4 floats) += A(4regs) * B(2regs)
#define MMA_TF32(ac, a0, a1, a2, a3, b0, b1)                                   \
    asm volatile("mma.sync.aligned.m16n8k8.row.col.f32.tf32.tf32.f32 "         \
                 "{%0,%1,%2,%3}, {%4,%5,%6,%7}, {%8,%9}, {%0,%1,%2,%3};"       \
                 : "+f"(ac[0]), "+f"(ac[1]), "+f"(ac[2]), "+f"(ac[3])          \
                 : "r"(a0), "r"(a1), "r"(a2), "r"(a3), "r"(b0), "r"(b1))

// Fragment load + 16 mma for one k8 slice from As[16][PITCH], Bs[16][PITCH].
// mW: warp m offset (0..96), nW: warp n offset (0/64), lr=lane/4, lc=lane%4.
#define MMA_K8(As_, Bs_, kk)                                                   \
    {                                                                          \
        unsigned a[2][4], b[8][2];                                             \
        _Pragma("unroll")                                                      \
        for (int ma = 0; ma < 2; ma++) {                                       \
            int m0 = mW + ma * 16 + lr;                                        \
            a[ma][0] = __float_as_uint(As_[(kk) + lc    ][m0]);                \
            a[ma][1] = __float_as_uint(As_[(kk) + lc    ][m0 + 8]);            \
            a[ma][2] = __float_as_uint(As_[(kk) + lc + 4][m0]);                \
            a[ma][3] = __float_as_uint(As_[(kk) + lc + 4][m0 + 8]);            \
        }                                                                      \
        _Pragma("unroll")                                                      \
        for (int na = 0; na < 8; na++) {                                       \
            int n0 = nW + na * 8 + lr;                                         \
            b[na][0] = __float_as_uint(Bs_[(kk) + lc    ][n0]);                \
            b[na][1] = __float_as_uint(Bs_[(kk) + lc + 4][n0]);                \
        }                                                                      \
        _Pragma("unroll")                                                      \
        for (int ma = 0; ma < 2; ma++)                                         \
            _Pragma("unroll")                                                  \
            for (int na = 0; na < 8; na++)                                     \
                MMA_TF32(acc[ma][na], a[ma][0], a[ma][1], a[ma][2], a[ma][3],  \
                         b[na][0], b[na][1]);                                  \
    }

// ---------------------------------------------------------------------------
// GroupNorm
// ---------------------------------------------------------------------------
__global__ void __launch_bounds__(256) gn_kernel(const float* __restrict__ x,
                                                 const float* __restrict__ w,
                                                 const float* __restrict__ bgn) {
    const int bg = blockIdx.x;
    const int bb = bg >> 5;
    const int g  = bg & 31;
    const int GSIZE = CPG * Nn;
    const size_t base = (size_t)(bb * Cc + g * CPG) * Nn;
    const float* xp = x + base;

    float s = 0.f, s2 = 0.f;
    for (int i = threadIdx.x; i < GSIZE; i += 256) {
        float v = xp[i];
        s += v; s2 += v * v;
    }
    __shared__ float r1[8], r2[8];
    __shared__ float sh_mean, sh_rstd;
    #pragma unroll
    for (int o = 16; o; o >>= 1) {
        s  += __shfl_xor_sync(0xffffffffu, s,  o);
        s2 += __shfl_xor_sync(0xffffffffu, s2, o);
    }
    if ((threadIdx.x & 31) == 0) { r1[threadIdx.x >> 5] = s; r2[threadIdx.x >> 5] = s2; }
    __syncthreads();
    if (threadIdx.x == 0) {
        s = 0.f; s2 = 0.f;
        #pragma unroll
        for (int i = 0; i < 8; i++) { s += r1[i]; s2 += r2[i]; }
        float mean = s * (1.f / GSIZE);
        float var  = s2 * (1.f / GSIZE) - mean * mean;
        sh_mean = mean;
        sh_rstd = rsqrtf(var + EPSf);
    }
    __syncthreads();
    const float mean = sh_mean, rstd = sh_rstd;
    for (int i = threadIdx.x; i < GSIZE; i += 256) {
        int c = g * CPG + (i >> 12);
        g_hs[base + i] = (xp[i] - mean) * rstd * w[c] + bgn[c];
    }
}

// ---------------------------------------------------------------------------
// QKV projections (NN, tf32 mma): out[m][n] = sum_k W[m][k]*hs[k][n] + b[m]
// ---------------------------------------------------------------------------
__global__ void __launch_bounds__(256, 2) qkv_kernel(const float* __restrict__ Wq,
                                                     const float* __restrict__ bq,
                                                     const float* __restrict__ Wk,
                                                     const float* __restrict__ bk,
                                                     const float* __restrict__ Wv,
                                                     const float* __restrict__ bv) {
    const int z  = blockIdx.z;
    const int which = z >> 2;
    const int bb    = z & 3;
    const float* A;  const float* bias;  float* Cm;
    if (which == 0)      { A = Wq; bias = bq; Cm = g_q; }
    else if (which == 1) { A = Wk; bias = bk; Cm = g_k; }
    else                 { A = Wv; bias = bv; Cm = g_v; }
    const float* Bm = g_hs + (size_t)bb * Cc * Nn;
    Cm += (size_t)bb * Cc * Nn;

    __shared__ float As[16][PITCH];
    __shared__ float Bs[16][PITCH];
    float acc[2][8][4];
    #pragma unroll
    for (int i = 0; i < 2; i++)
        #pragma unroll
        for (int j = 0; j < 8; j++)
            #pragma unroll
            for (int r = 0; r < 4; r++) acc[i][j][r] = 0.f;

    const int tid = threadIdx.x;
    const int lane = tid & 31, wid = tid >> 5;
    const int lr = lane >> 2, lc = lane & 3;
    const int mW = (wid & 3) * 32, nW = (wid >> 2) * 64;
    const int rowBase = blockIdx.y * 128;
    const int colBase = blockIdx.x * 128;

    for (int k0 = 0; k0 < Cc; k0 += 16) {
        #pragma unroll
        for (int l = tid * 4; l < 2048; l += 1024) {
            int m  = l >> 4, kk = l & 15;
            float4 a4 = cvt_tf32_4(*(const float4*)(A + (size_t)(rowBase + m) * Cc + k0 + kk));
            As[kk + 0][m] = a4.x; As[kk + 1][m] = a4.y;
            As[kk + 2][m] = a4.z; As[kk + 3][m] = a4.w;
            int kb = l >> 7, j = l & 127;
            *(float4*)&Bs[kb][j] =
                cvt_tf32_4(*(const float4*)(Bm + (size_t)(k0 + kb) * Nn + colBase + j));
        }
        __syncthreads();
        MMA_K8(As, Bs, 0)
        MMA_K8(As, Bs, 8)
        __syncthreads();
    }
    #pragma unroll
    for (int ma = 0; ma < 2; ma++) {
        int m0 = rowBase + mW + ma * 16 + lr;
        float b0 = bias[m0], b1 = bias[m0 + 8];
        #pragma unroll
        for (int na = 0; na < 8; na++) {
            int cI = colBase + nW + na * 8 + 2 * lc;
            float2 v0 = {acc[ma][na][0] + b0, acc[ma][na][1] + b0};
            float2 v1 = {acc[ma][na][2] + b1, acc[ma][na][3] + b1};
            *(float2*)(Cm + (size_t)m0 * Nn + cI)       = v0;
            *(float2*)(Cm + (size_t)(m0 + 8) * Nn + cI) = v1;
        }
    }
}

// ---------------------------------------------------------------------------
// Scores (TN, tf32 mma, double-buffered): S = scale * Q^T K
// ---------------------------------------------------------------------------
__global__ void __launch_bounds__(256, 2) scores_kernel() {
    const int bb = blockIdx.z;
    const float* Q  = g_q + (size_t)bb * Cc * Nn;
    const float* Kt = g_k + (size_t)bb * Cc * Nn;
    float* S = g_p + (size_t)bb * Nn * Nn;

    __shared__ float As[2][16][PITCH];
    __shared__ float Bs[2][16][PITCH];
    float acc[2][8][4];
    #pragma unroll
    for (int i = 0; i < 2; i++)
        #pragma unroll
        for (int j = 0; j < 8; j++)
            #pragma unroll
            for (int r = 0; r < 4; r++) acc[i][j][r] = 0.f;

    const int tid = threadIdx.x;
    const int lane = tid & 31, wid = tid >> 5;
    const int lr = lane >> 2, lc = lane & 3;
    const int mW = (wid & 3) * 32, nW = (wid >> 2) * 64;
    const int rowBase = blockIdx.y * 128;
    const int colBase = blockIdx.x * 128;

    const int l0 = tid * 4,       l1 = tid * 4 + 1024;
    const int kkA = l0 >> 7, iiA = l0 & 127;
    const int kkB = l1 >> 7, iiB = l1 & 127;

    *(float4*)&As[0][kkA][iiA] = cvt_tf32_4(*(const float4*)(Q  + (size_t)kkA * Nn + rowBase + iiA));
    *(float4*)&Bs[0][kkA][iiA] = cvt_tf32_4(*(const float4*)(Kt + (size_t)kkA * Nn + colBase + iiA));
    *(float4*)&As[0][kkB][iiB] = cvt_tf32_4(*(const float4*)(Q  + (size_t)kkB * Nn + rowBase + iiB));
    *(float4*)&Bs[0][kkB][iiB] = cvt_tf32_4(*(const float4*)(Kt + (size_t)kkB * Nn + colBase + iiB));
    __syncthreads();

    int buf = 0;
    for (int k0 = 0; k0 < Cc; k0 += 16) {
        if (k0 + 16 < Cc) {
            const int nb = buf ^ 1, kn = k0 + 16;
            *(float4*)&As[nb][kkA][iiA] = cvt_tf32_4(*(const float4*)(Q  + (size_t)(kn + kkA) * Nn + rowBase + iiA));
            *(float4*)&Bs[nb][kkA][iiA] = cvt_tf32_4(*(const float4*)(Kt + (size_t)(kn + kkA) * Nn + colBase + iiA));
            *(float4*)&As[nb][kkB][iiB] = cvt_tf32_4(*(const float4*)(Q  + (size_t)(kn + kkB) * Nn + rowBase + iiB));
            *(float4*)&Bs[nb][kkB][iiB] = cvt_tf32_4(*(const float4*)(Kt + (size_t)(kn + kkB) * Nn + colBase + iiB));
        }
        MMA_K8(As[buf], Bs[buf], 0)
        MMA_K8(As[buf], Bs[buf], 8)
        __syncthreads();
        buf ^= 1;
    }
    #pragma unroll
    for (int ma = 0; ma < 2; ma++) {
        int m0 = rowBase + mW + ma * 16 + lr;
        #pragma unroll
        for (int na = 0; na < 8; na++) {
            int cI = colBase + nW + na * 8 + 2 * lc;
            float2 v0 = {acc[ma][na][0] * SCALEf, acc[ma][na][1] * SCALEf};
            float2 v1 = {acc[ma][na][2] * SCALEf, acc[ma][na][3] * SCALEf};
            *(float2*)(S + (size_t)m0 * Nn + cI)       = v0;
            *(float2*)(S + (size_t)(m0 + 8) * Nn + cI) = v1;
        }
    }
}

// ---------------------------------------------------------------------------
// Row softmax
// ---------------------------------------------------------------------------
__global__ void __launch_bounds__(256) softmax_kernel() {
    __shared__ float buf[Nn];
    __shared__ float red[8];
    float* p = g_p + (size_t)blockIdx.x * Nn;
    const int tid = threadIdx.x;

    float m = -3.4e38f;
    for (int i = tid; i < Nn; i += 256) { float v = p[i]; buf[i] = v; m = fmaxf(m, v); }
    #pragma unroll
    for (int o = 16; o; o >>= 1) m = fmaxf(m, __shfl_xor_sync(0xffffffffu, m, o));
    if ((tid & 31) == 0) red[tid >> 5] = m;
    __syncthreads();
    if (tid < 8) {
        m = red[tid];
        #pragma unroll
        for (int o = 4; o; o >>= 1) m = fmaxf(m, __shfl_xor_sync(0xffu, m, o));
        if (tid == 0) red[0] = m;
    }
    __syncthreads();
    m = red[0];
    __syncthreads();

    float sum = 0.f;
    for (int i = tid; i < Nn; i += 256) { float e = __expf(buf[i] - m); buf[i] = e; sum += e; }
    #pragma unroll
    for (int o = 16; o; o >>= 1) sum += __shfl_xor_sync(0xffffffffu, sum, o);
    if ((tid & 31) == 0) red[tid >> 5] = sum;
    __syncthreads();
    if (tid < 8) {
        sum = red[tid];
        #pragma unroll
        for (int o = 4; o; o >>= 1) sum += __shfl_xor_sync(0xffu, sum, o);
        if (tid == 0) red[0] = sum;
    }
    __syncthreads();
    const float inv = 1.f / red[0];
    for (int i = tid; i < Nn; i += 256) p[i] = buf[i] * inv;
}

// ---------------------------------------------------------------------------
// AO (NT, tf32 mma, double-buffered): AO[c][n] = sum_j V[c][j] * P[n][j]
// ---------------------------------------------------------------------------
__global__ void __launch_bounds__(256, 2) ao_kernel() {
    const int bb = blockIdx.z;
    const float* Vp = g_v + (size_t)bb * Cc * Nn;
    const float* Pp = g_p + (size_t)bb * Nn * Nn;
    float* AO = g_ao + (size_t)bb * Cc * Nn;

    __shared__ float As[2][16][PITCH];
    __shared__ float Bs[2][16][PITCH];
    float acc[2][8][4];
    #pragma unroll
    for (int i = 0; i < 2; i++)
        #pragma unroll
        for (int j = 0; j < 8; j++)
            #pragma unroll
            for (int r = 0; r < 4; r++) acc[i][j][r] = 0.f;

    const int tid = threadIdx.x;
    const int lane = tid & 31, wid = tid >> 5;
    const int lr = lane >> 2, lc = lane & 3;
    const int mW = (wid & 3) * 32, nW = (wid >> 2) * 64;
    const int rowBase = blockIdx.y * 128;   // c
    const int colBase = blockIdx.x * 128;   // n

    const int l0 = tid * 4,        l1 = tid * 4 + 1024;
    const int m0i = l0 >> 4, kk0 = l0 & 15;
    const int m1i = l1 >> 4, kk1 = l1 & 15;

    {
        float4 a0 = cvt_tf32_4(*(const float4*)(Vp + (size_t)(rowBase + m0i) * Nn + kk0));
        As[0][kk0 + 0][m0i] = a0.x; As[0][kk0 + 1][m0i] = a0.y;
        As[0][kk0 + 2][m0i] = a0.z; As[0][kk0 + 3][m0i] = a0.w;
        float4 b0 = cvt_tf32_4(*(const float4*)(Pp + (size_t)(colBase + m0i) * Nn + kk0));
        Bs[0][kk0 + 0][m0i] = b0.x; Bs[0][kk0 + 1][m0i] = b0.y;
        Bs[0][kk0 + 2][m0i] = b0.z; Bs[0][kk0 + 3][m0i] = b0.w;
        float4 a1 = cvt_tf32_4(*(const float4*)(Vp + (size_t)(rowBase + m1i) * Nn + kk1));
        As[0][kk1 + 0][m1i] = a1.x; As[0][kk1 + 1][m1i] = a1.y;
        As[0][kk1 + 2][m1i] = a1.z; As[0][kk1 + 3][m1i] = a1.w;
        float4 b1 = cvt_tf32_4(*(const float4*)(Pp + (size_t)(colBase + m1i) * Nn + kk1));
        Bs[0][kk1 + 0][m1i] = b1.x; Bs[0][kk1 + 1][m1i] = b1.y;
        Bs[0][kk1 + 2][m1i] = b1.z; Bs[0][kk1 + 3][m1i] = b1.w;
    }
    __syncthreads();

    int buf = 0;
    for (int k0 = 0; k0 < Nn; k0 += 16) {
        if (k0 + 16 < Nn) {
            const int nb = buf ^ 1, kn = k0 + 16;
            float4 a0 = cvt_tf32_4(*(const float4*)(Vp + (size_t)(rowBase + m0i) * Nn + kn + kk0));
            As[nb][kk0 + 0][m0i] = a0.x; As[nb][kk0 + 1][m0i] = a0.y;
            As[nb][kk0 + 2][m0i] = a0.z; As[nb][kk0 + 3][m0i] = a0.w;
            float4 b0 = cvt_tf32_4(*(const float4*)(Pp + (size_t)(colBase + m0i) * Nn + kn + kk0));
            Bs[nb][kk0 + 0][m0i] = b0.x; Bs[nb][kk0 + 1][m0i] = b0.y;
            Bs[nb][kk0 + 2][m0i] = b0.z; Bs[nb][kk0 + 3][m0i] = b0.w;
            float4 a1 = cvt_tf32_4(*(const float4*)(Vp + (size_t)(rowBase + m1i) * Nn + kn + kk1));
            As[nb][kk1 + 0][m1i] = a1.x; As[nb][kk1 + 1][m1i] = a1.y;
            As[nb][kk1 + 2][m1i] = a1.z; As[nb][kk1 + 3][m1i] = a1.w;
            float4 b1 = cvt_tf32_4(*(const float4*)(Pp + (size_t)(colBase + m1i) * Nn + kn + kk1));
            Bs[nb][kk1 + 0][m1i] = b1.x; Bs[nb][kk1 + 1][m1i] = b1.y;
            Bs[nb][kk1 + 2][m1i] = b1.z; Bs[nb][kk1 + 3][m1i] = b1.w;
        }
        MMA_K8(As[buf], Bs[buf], 0)
        MMA_K8(As[buf], Bs[buf], 8)
        __syncthreads();
        buf ^= 1;
    }
    #pragma unroll
    for (int ma = 0; ma < 2; ma++) {
        int m0 = rowBase + mW + ma * 16 + lr;
        #pragma unroll
        for (int na = 0; na < 8; na++) {
            int cI = colBase + nW + na * 8 + 2 * lc;
            float2 v0 = {acc[ma][na][0], acc[ma][na][1]};
            float2 v1 = {acc[ma][na][2], acc[ma][na][3]};
            *(float2*)(AO + (size_t)m0 * Nn + cI)       = v0;
            *(float2*)(AO + (size_t)(m0 + 8) * Nn + cI) = v1;
        }
    }
}

// ---------------------------------------------------------------------------
// Output projection (NN, tf32 mma) + residual epilogue
// ---------------------------------------------------------------------------
__global__ void __launch_bounds__(256, 2) outproj_kernel(const float* __restrict__ Wo,
                                                         const float* __restrict__ bo,
                                                         const float* __restrict__ x,
                                                         float* __restrict__ out) {
    const int bb = blockIdx.z;
    const float* Bm = g_ao + (size_t)bb * Cc * Nn;

    __shared__ float As[16][PITCH];
    __shared__ float Bs[16][PITCH];
    float acc[2][8][4];
    #pragma unroll
    for (int i = 0; i < 2; i++)
        #pragma unroll
        for (int j = 0; j < 8; j++)
            #pragma unroll
            for (int r = 0; r < 4; r++) acc[i][j][r] = 0.f;

    const int tid = threadIdx.x;
    const int lane = tid & 31, wid = tid >> 5;
    const int lr = lane >> 2, lc = lane & 3;
    const int mW = (wid & 3) * 32, nW = (wid >> 2) * 64;
    const int rowBase = blockIdx.y * 128;
    const int colBase = blockIdx.x * 128;

    for (int k0 = 0; k0 < Cc; k0 += 16) {
        #pragma unroll
        for (int l = tid * 4; l < 2048; l += 1024) {
            int m  = l >> 4, kk = l & 15;
            float4 a4 = cvt_tf32_4(*(const float4*)(Wo + (size_t)(rowBase + m) * Cc + k0 + kk));
            As[kk + 0][m] = a4.x; As[kk + 1][m] = a4.y;
            As[kk + 2][m] = a4.z; As[kk + 3][m] = a4.w;
            int kb = l >> 7, j = l & 127;
            *(float4*)&Bs[kb][j] =
                cvt_tf32_4(*(const float4*)(Bm + (size_t)(k0 + kb) * Nn + colBase + j));
        }
        __syncthreads();
        MMA_K8(As, Bs, 0)
        MMA_K8(As, Bs, 8)
        __syncthreads();
    }
    #pragma unroll
    for (int ma = 0; ma < 2; ma++) {
        int m0 = rowBase + mW + ma * 16 + lr;
        float b0 = bo[m0], b1 = bo[m0 + 8];
        #pragma unroll
        for (int na = 0; na < 8; na++) {
            int cI = colBase + nW + na * 8 + 2 * lc;
            size_t i0 = (size_t)(bb * Cc + m0) * Nn + cI;
            size_t i1 = (size_t)(bb * Cc + m0 + 8) * Nn + cI;
            float2 x0 = *(const float2*)(x + i0);
            float2 x1 = *(const float2*)(x + i1);
            float2 v0 = {(x0.x + acc[ma][na][0] + b0) * RSQRT2f,
                         (x0.y + acc[ma][na][1] + b0) * RSQRT2f};
            float2 v1 = {(x1.x + acc[ma][na][2] + b1) * RSQRT2f,
                         (x1.y + acc[ma][na][3] + b1) * RSQRT2f};
            *(float2*)(out + i0) = v0;
            *(float2*)(out + i1) = v1;
        }
    }
}

// ---------------------------------------------------------------------------
extern "C" void kernel_launch(void* const* d_in, const int* in_sizes, int n_in,
                              void* d_out, int out_size) {
    const float* x  = (const float*)d_in[0];
    const float* gw = (const float*)d_in[1];
    const float* gb = (const float*)d_in[2];
    const float* Wq = (const float*)d_in[3];
    const float* bq = (const float*)d_in[4];
    const float* Wk = (const float*)d_in[5];
    const float* bk = (const float*)d_in[6];
    const float* Wv = (const float*)d_in[7];
    const float* bv = (const float*)d_in[8];
    const float* Wo = (const float*)d_in[9];
    const float* bo = (const float*)d_in[10];
    float* out = (float*)d_out;

    gn_kernel<<<Bn * Gg, 256>>>(x, gw, gb);
    qkv_kernel<<<dim3(Nn / 128, Cc / 128, 12), 256>>>(Wq, bq, Wk, bk, Wv, bv);
    scores_kernel<<<dim3(Nn / 128, Nn / 128, Bn), 256>>>();
    softmax_kernel<<<Bn * Nn, 256>>>();
    ao_kernel<<<dim3(Nn / 128, Cc / 128, Bn), 256>>>();
    outproj_kernel<<<dim3(Nn / 128, Cc / 128, Bn), 256>>>(Wo, bo, x, out);
}

// round 6
// speedup vs baseline: 3.5075x; 1.7183x over previous
#include <cuda_runtime.h>
#include <cuda_bf16.h>
#include <cstdint>

#define Bn 4
#define Cc 256
#define Nn 4096
#define EPSf 1e-6f
#define SCALEf 0.0625f
#define RSQRT2f 0.70710678118654752440f
#define PITCH 136   // fp32 smem pitch for tf32 mma kernels
#define BP 40       // bf16 tile pitch (elements): 80 bytes/row, conflict-free LDSM

// Scratch (device globals — allocation-free contract).
__device__ float         g_hs[Bn * Cc * Nn];              // groupnorm out [B][C][N] fp32
__device__ __nv_bfloat16 g_qb[Bn * Nn * Cc];              // Q transposed [B][N][C] bf16
__device__ __nv_bfloat16 g_kb[Bn * Nn * Cc];              // K transposed [B][N][C] bf16
__device__ __nv_bfloat16 g_vb[Bn * Cc * Nn];              // V [B][C][N] bf16
__device__ float         g_p [(size_t)Bn * Nn * Nn];      // scores fp32 [B][N][N]
__device__ __nv_bfloat16 g_pb[(size_t)Bn * Nn * Nn];      // probs bf16 [B][N][N]
__device__ float         g_ao[Bn * Cc * Nn];              // attn out fp32 [B][C][N]

// ---------------- common helpers ----------------
static __device__ __forceinline__ uint32_t smem_u32(const void* p) {
    uint32_t a;
    asm("{ .reg .u64 t; cvta.to.shared.u64 t, %1; cvt.u32.u64 %0, t; }" : "=r"(a) : "l"(p));
    return a;
}

#define LDSM4(r0, r1, r2, r3, addr)                                            \
    asm volatile("ldmatrix.sync.aligned.m8n8.x4.shared.b16 {%0,%1,%2,%3}, [%4];" \
                 : "=r"(r0), "=r"(r1), "=r"(r2), "=r"(r3) : "r"(addr))

#define MMA_BF16(ac, a, b0, b1)                                                \
    asm volatile("mma.sync.aligned.m16n8k16.row.col.f32.bf16.bf16.f32 "        \
                 "{%0,%1,%2,%3}, {%4,%5,%6,%7}, {%8,%9}, {%0,%1,%2,%3};"       \
                 : "+f"((ac)[0]), "+f"((ac)[1]), "+f"((ac)[2]), "+f"((ac)[3])  \
                 : "r"((a)[0]), "r"((a)[1]), "r"((a)[2]), "r"((a)[3]),         \
                   "r"(b0), "r"(b1))

#define CP_COMMIT() asm volatile("cp.async.commit_group;" ::: "memory")
#define CP_WAIT(n)  asm volatile("cp.async.wait_group %0;" :: "n"(n) : "memory")

// cp.async one 128x32 bf16 tile (src row-major, stride STR elements) into
// smem tile of pitch BP (80 bytes/row). 256 threads, 2 x 16B per thread.
template <int STR>
static __device__ __forceinline__ void cp_tile(uint32_t dstBase, const __nv_bfloat16* src,
                                               int r0, int k0, int tid) {
    #pragma unroll
    for (int p = 0; p < 2; p++) {
        int idx = tid + p * 256;
        int row = idx >> 2, seg = idx & 3;
        uint32_t d = dstBase + row * 80 + seg * 16;
        const void* g = src + (size_t)(r0 + row) * STR + k0 + seg * 8;
        asm volatile("cp.async.ca.shared.global [%0], [%1], 16;" :: "r"(d), "l"(g));
    }
}

// One k32 chunk of bf16 mma for a 32(m) x 64(n) warp tile.
static __device__ __forceinline__ void bf16_compute(uint32_t aBase, uint32_t bBase,
                                                    int lane, int mW, int nW,
                                                    float acc[2][8][4]) {
    #pragma unroll
    for (int ks = 0; ks < 2; ks++) {
        const int kb = ks * 32 + ((lane >> 4) << 4);   // byte offset in row
        uint32_t a[2][4];
        #pragma unroll
        for (int ma = 0; ma < 2; ma++) {
            uint32_t ad = aBase + (mW + ma * 16 + (lane & 15)) * 80 + kb;
            LDSM4(a[ma][0], a[ma][1], a[ma][2], a[ma][3], ad);
        }
        #pragma unroll
        for (int nb = 0; nb < 4; nb++) {
            uint32_t b0, b1, b2, b3;
            uint32_t bd = bBase + (nW + nb * 16 + (lane & 15)) * 80 + kb;
            LDSM4(b0, b1, b2, b3, bd);
            #pragma unroll
            for (int ma = 0; ma < 2; ma++) {
                MMA_BF16(acc[ma][nb * 2 + 0], a[ma], b0, b2);
                MMA_BF16(acc[ma][nb * 2 + 1], a[ma], b1, b3);
            }
        }
    }
}

// ---------------- GroupNorm ----------------
__global__ void __launch_bounds__(256) gn_kernel(const float* __restrict__ x,
                                                 const float* __restrict__ w,
                                                 const float* __restrict__ bgn) {
    const int bb = blockIdx.x >> 5, g = blockIdx.x & 31;
    const int GSIZE = 8 * Nn;
    const size_t base = (size_t)(bb * Cc + g * 8) * Nn;
    const float* xp = x + base;
    float s = 0.f, s2 = 0.f;
    for (int i = threadIdx.x; i < GSIZE; i += 256) { float v = xp[i]; s += v; s2 += v * v; }
    __shared__ float r1[8], r2[8], shm, shr;
    #pragma unroll
    for (int o = 16; o; o >>= 1) {
        s += __shfl_xor_sync(~0u, s, o); s2 += __shfl_xor_sync(~0u, s2, o);
    }
    if ((threadIdx.x & 31) == 0) { r1[threadIdx.x >> 5] = s; r2[threadIdx.x >> 5] = s2; }
    __syncthreads();
    if (threadIdx.x == 0) {
        s = 0.f; s2 = 0.f;
        #pragma unroll
        for (int i = 0; i < 8; i++) { s += r1[i]; s2 += r2[i]; }
        float mean = s / GSIZE, var = s2 / GSIZE - mean * mean;
        shm = mean; shr = rsqrtf(var + EPSf);
    }
    __syncthreads();
    const float mean = shm, rstd = shr;
    for (int i = threadIdx.x; i < GSIZE; i += 256) {
        int c = g * 8 + (i >> 12);
        g_hs[base + i] = (xp[i] - mean) * rstd * w[c] + bgn[c];
    }
}

// ---------------- tf32 mma.sync machinery (qkv / outproj) ----------------
__device__ __forceinline__ float cvt_tf32(float x) {
    unsigned u;
    asm("cvt.rna.tf32.f32 %0, %1;" : "=r"(u) : "f"(x));
    return __uint_as_float(u);
}
__device__ __forceinline__ float4 cvt_tf32_4(float4 v) {
    float4 r;
    r.x = cvt_tf32(v.x); r.y = cvt_tf32(v.y); r.z = cvt_tf32(v.z); r.w = cvt_tf32(v.w);
    return r;
}
#define MMA_TF32(ac, a0, a1, a2, a3, b0, b1)                                   \
    asm volatile("mma.sync.aligned.m16n8k8.row.col.f32.tf32.tf32.f32 "         \
                 "{%0,%1,%2,%3}, {%4,%5,%6,%7}, {%8,%9}, {%0,%1,%2,%3};"       \
                 : "+f"(ac[0]), "+f"(ac[1]), "+f"(ac[2]), "+f"(ac[3])          \
                 : "r"(a0), "r"(a1), "r"(a2), "r"(a3), "r"(b0), "r"(b1))
#define MMA_K8(As_, Bs_, kk)                                                   \
    {                                                                          \
        unsigned a[2][4], b[8][2];                                             \
        _Pragma("unroll")                                                      \
        for (int ma = 0; ma < 2; ma++) {                                       \
            int m0 = mW + ma * 16 + lr;                                        \
            a[ma][0] = __float_as_uint(As_[(kk) + lc    ][m0]);                \
            a[ma][1] = __float_as_uint(As_[(kk) + lc    ][m0 + 8]);            \
            a[ma][2] = __float_as_uint(As_[(kk) + lc + 4][m0]);                \
            a[ma][3] = __float_as_uint(As_[(kk) + lc + 4][m0 + 8]);            \
        }                                                                      \
        _Pragma("unroll")                                                      \
        for (int na = 0; na < 8; na++) {                                       \
            int n0 = nW + na * 8 + lr;                                         \
            b[na][0] = __float_as_uint(Bs_[(kk) + lc    ][n0]);                \
            b[na][1] = __float_as_uint(Bs_[(kk) + lc + 4][n0]);                \
        }                                                                      \
        _Pragma("unroll")                                                      \
        for (int ma = 0; ma < 2; ma++)                                         \
            _Pragma("unroll")                                                  \
            for (int na = 0; na < 8; na++)                                     \
                MMA_TF32(acc[ma][na], a[ma][0], a[ma][1], a[ma][2], a[ma][3],  \
                         b[na][0], b[na][1]);                                  \
    }

// qkv: out = W * hs + b. Q,K stored transposed bf16 [N][C]; V bf16 [C][N].
__global__ void __launch_bounds__(256, 2) qkv_kernel(const float* __restrict__ Wq,
                                                     const float* __restrict__ bq,
                                                     const float* __restrict__ Wk,
                                                     const float* __restrict__ bk,
                                                     const float* __restrict__ Wv,
                                                     const float* __restrict__ bv) {
    const int z = blockIdx.z, which = z >> 2, bb = z & 3;
    const float* A; const float* bias; __nv_bfloat16* Cb;
    if (which == 0)      { A = Wq; bias = bq; Cb = g_qb + (size_t)bb * Nn * Cc; }
    else if (which == 1) { A = Wk; bias = bk; Cb = g_kb + (size_t)bb * Nn * Cc; }
    else                 { A = Wv; bias = bv; Cb = g_vb + (size_t)bb * Cc * Nn; }
    const float* Bm = g_hs + (size_t)bb * Cc * Nn;

    __shared__ float As[16][PITCH], Bs[16][PITCH];
    float acc[2][8][4] = {};
    const int tid = threadIdx.x, lane = tid & 31, wid = tid >> 5;
    const int lr = lane >> 2, lc = lane & 3;
    const int mW = (wid & 3) * 32, nW = (wid >> 2) * 64;
    const int rowB = blockIdx.y * 128, colB = blockIdx.x * 128;

    for (int k0 = 0; k0 < Cc; k0 += 16) {
        #pragma unroll
        for (int l = tid * 4; l < 2048; l += 1024) {
            int m = l >> 4, kk = l & 15;
            float4 a4 = cvt_tf32_4(*(const float4*)(A + (size_t)(rowB + m) * Cc + k0 + kk));
            As[kk + 0][m] = a4.x; As[kk + 1][m] = a4.y; As[kk + 2][m] = a4.z; As[kk + 3][m] = a4.w;
            int kb = l >> 7, j = l & 127;
            *(float4*)&Bs[kb][j] = cvt_tf32_4(*(const float4*)(Bm + (size_t)(k0 + kb) * Nn + colB + j));
        }
        __syncthreads();
        MMA_K8(As, Bs, 0)
        MMA_K8(As, Bs, 8)
        __syncthreads();
    }
    #pragma unroll
    for (int ma = 0; ma < 2; ma++) {
        int m0 = rowB + mW + ma * 16 + lr;
        float b0 = bias[m0], b1 = bias[m0 + 8];
        #pragma unroll
        for (int na = 0; na < 8; na++) {
            int cI = colB + nW + na * 8 + 2 * lc;
            if (which < 2) {   // transposed bf16 store [N][C]
                Cb[(size_t)cI * Cc + m0]           = __float2bfloat16(acc[ma][na][0] + b0);
                Cb[(size_t)(cI + 1) * Cc + m0]     = __float2bfloat16(acc[ma][na][1] + b0);
                Cb[(size_t)cI * Cc + m0 + 8]       = __float2bfloat16(acc[ma][na][2] + b1);
                Cb[(size_t)(cI + 1) * Cc + m0 + 8] = __float2bfloat16(acc[ma][na][3] + b1);
            } else {           // V bf16 [C][N], vectorized pairs
                __nv_bfloat162 p0 = __floats2bfloat162_rn(acc[ma][na][0] + b0, acc[ma][na][1] + b0);
                __nv_bfloat162 p1 = __floats2bfloat162_rn(acc[ma][na][2] + b1, acc[ma][na][3] + b1);
                *(__nv_bfloat162*)(Cb + (size_t)m0 * Nn + cI)       = p0;
                *(__nv_bfloat162*)(Cb + (size_t)(m0 + 8) * Nn + cI) = p1;
            }
        }
    }
}

// ---------------- scores: S = scale * Qt Kt^T  (bf16 mma, cp.async DB) ----------------
__global__ void __launch_bounds__(256, 2) scores_bf_kernel() {
    const int tid = threadIdx.x, lane = tid & 31, wid = tid >> 5;
    const int lr = lane >> 2, lc = lane & 3;
    const int mW = (wid & 3) * 32, nW = (wid >> 2) * 64;
    const int bb = blockIdx.z, rowB = blockIdx.y * 128, colB = blockIdx.x * 128;
    const __nv_bfloat16* Qt = g_qb + (size_t)bb * Nn * Cc;
    const __nv_bfloat16* Kt = g_kb + (size_t)bb * Nn * Cc;
    float* S = g_p + (size_t)bb * Nn * Nn;

    __shared__ __align__(16) __nv_bfloat16 As[2][128 * BP];
    __shared__ __align__(16) __nv_bfloat16 Bs[2][128 * BP];
    float acc[2][8][4] = {};
    uint32_t aB[2] = {smem_u32(As[0]), smem_u32(As[1])};
    uint32_t bB[2] = {smem_u32(Bs[0]), smem_u32(Bs[1])};

    cp_tile<Cc>(aB[0], Qt, rowB, 0, tid);
    cp_tile<Cc>(bB[0], Kt, colB, 0, tid);
    CP_COMMIT();
    #pragma unroll 1
    for (int c = 0; c < 8; c++) {
        if (c + 1 < 8) {
            cp_tile<Cc>(aB[(c + 1) & 1], Qt, rowB, (c + 1) * 32, tid);
            cp_tile<Cc>(bB[(c + 1) & 1], Kt, colB, (c + 1) * 32, tid);
            CP_COMMIT();
            CP_WAIT(1);
        } else {
            CP_WAIT(0);
        }
        __syncthreads();
        bf16_compute(aB[c & 1], bB[c & 1], lane, mW, nW, acc);
        __syncthreads();
    }
    #pragma unroll
    for (int ma = 0; ma < 2; ma++) {
        int m0 = rowB + mW + ma * 16 + lr;
        #pragma unroll
        for (int idx = 0; idx < 8; idx++) {
            int cI = colB + nW + (idx >> 1) * 16 + (idx & 1) * 8 + 2 * lc;
            float2 v0 = {acc[ma][idx][0] * SCALEf, acc[ma][idx][1] * SCALEf};
            float2 v1 = {acc[ma][idx][2] * SCALEf, acc[ma][idx][3] * SCALEf};
            *(float2*)(S + (size_t)m0 * Nn + cI)       = v0;
            *(float2*)(S + (size_t)(m0 + 8) * Nn + cI) = v1;
        }
    }
}

// ---------------- softmax: read S fp32, write P bf16 ----------------
__global__ void __launch_bounds__(256) softmax_kernel() {
    __shared__ float buf[Nn];
    __shared__ float red[8];
    const float* p = g_p + (size_t)blockIdx.x * Nn;
    __nv_bfloat16* pb = g_pb + (size_t)blockIdx.x * Nn;
    const int tid = threadIdx.x;
    float m = -3.4e38f;
    for (int i = tid; i < Nn; i += 256) { float v = p[i]; buf[i] = v; m = fmaxf(m, v); }
    #pragma unroll
    for (int o = 16; o; o >>= 1) m = fmaxf(m, __shfl_xor_sync(~0u, m, o));
    if ((tid & 31) == 0) red[tid >> 5] = m;
    __syncthreads();
    if (tid < 8) {
        m = red[tid];
        #pragma unroll
        for (int o = 4; o; o >>= 1) m = fmaxf(m, __shfl_xor_sync(0xffu, m, o));
        if (tid == 0) red[0] = m;
    }
    __syncthreads();
    m = red[0];
    __syncthreads();
    float sum = 0.f;
    for (int i = tid; i < Nn; i += 256) { float e = __expf(buf[i] - m); buf[i] = e; sum += e; }
    #pragma unroll
    for (int o = 16; o; o >>= 1) sum += __shfl_xor_sync(~0u, sum, o);
    if ((tid & 31) == 0) red[tid >> 5] = sum;
    __syncthreads();
    if (tid < 8) {
        sum = red[tid];
        #pragma unroll
        for (int o = 4; o; o >>= 1) sum += __shfl_xor_sync(0xffu, sum, o);
        if (tid == 0) red[0] = sum;
    }
    __syncthreads();
    const float inv = 1.f / red[0];
    for (int i = tid * 2; i < Nn; i += 512)
        *(__nv_bfloat162*)(pb + i) = __floats2bfloat162_rn(buf[i] * inv, buf[i + 1] * inv);
}

// ---------------- ao: AO[c][n] = sum_j V[c][j] P[n][j]  (bf16 mma, cp.async DB) ----------------
__global__ void __launch_bounds__(256, 2) ao_bf_kernel() {
    const int tid = threadIdx.x, lane = tid & 31, wid = tid >> 5;
    const int lr = lane >> 2, lc = lane & 3;
    const int mW = (wid & 3) * 32, nW = (wid >> 2) * 64;
    const int bb = blockIdx.z, rowB = blockIdx.y * 128, colB = blockIdx.x * 128;
    const __nv_bfloat16* Vb = g_vb + (size_t)bb * Cc * Nn;
    const __nv_bfloat16* Pb = g_pb + (size_t)bb * Nn * Nn;
    float* AO = g_ao + (size_t)bb * Cc * Nn;

    __shared__ __align__(16) __nv_bfloat16 As[2][128 * BP];
    __shared__ __align__(16) __nv_bfloat16 Bs[2][128 * BP];
    float acc[2][8][4] = {};
    uint32_t aB[2] = {smem_u32(As[0]), smem_u32(As[1])};
    uint32_t bB[2] = {smem_u32(Bs[0]), smem_u32(Bs[1])};

    cp_tile<Nn>(aB[0], Vb, rowB, 0, tid);
    cp_tile<Nn>(bB[0], Pb, colB, 0, tid);
    CP_COMMIT();
    #pragma unroll 1
    for (int c = 0; c < 128; c++) {
        if (c + 1 < 128) {
            cp_tile<Nn>(aB[(c + 1) & 1], Vb, rowB, (c + 1) * 32, tid);
            cp_tile<Nn>(bB[(c + 1) & 1], Pb, colB, (c + 1) * 32, tid);
            CP_COMMIT();
            CP_WAIT(1);
        } else {
            CP_WAIT(0);
        }
        __syncthreads();
        bf16_compute(aB[c & 1], bB[c & 1], lane, mW, nW, acc);
        __syncthreads();
    }
    #pragma unroll
    for (int ma = 0; ma < 2; ma++) {
        int m0 = rowB + mW + ma * 16 + lr;
        #pragma unroll
        for (int idx = 0; idx < 8; idx++) {
            int cI = colB + nW + (idx >> 1) * 16 + (idx & 1) * 8 + 2 * lc;
            float2 v0 = {acc[ma][idx][0], acc[ma][idx][1]};
            float2 v1 = {acc[ma][idx][2], acc[ma][idx][3]};
            *(float2*)(AO + (size_t)m0 * Nn + cI)       = v0;
            *(float2*)(AO + (size_t)(m0 + 8) * Nn + cI) = v1;
        }
    }
}

// ---------------- outproj (tf32 mma) + residual ----------------
__global__ void __launch_bounds__(256, 2) outproj_kernel(const float* __restrict__ Wo,
                                                         const float* __restrict__ bo,
                                                         const float* __restrict__ x,
                                                         float* __restrict__ out) {
    const int bb = blockIdx.z;
    const float* Bm = g_ao + (size_t)bb * Cc * Nn;
    __shared__ float As[16][PITCH], Bs[16][PITCH];
    float acc[2][8][4] = {};
    const int tid = threadIdx.x, lane = tid & 31, wid = tid >> 5;
    const int lr = lane >> 2, lc = lane & 3;
    const int mW = (wid & 3) * 32, nW = (wid >> 2) * 64;
    const int rowB = blockIdx.y * 128, colB = blockIdx.x * 128;

    for (int k0 = 0; k0 < Cc; k0 += 16) {
        #pragma unroll
        for (int l = tid * 4; l < 2048; l += 1024) {
            int m = l >> 4, kk = l & 15;
            float4 a4 = cvt_tf32_4(*(const float4*)(Wo + (size_t)(rowB + m) * Cc + k0 + kk));
            As[kk + 0][m] = a4.x; As[kk + 1][m] = a4.y; As[kk + 2][m] = a4.z; As[kk + 3][m] = a4.w;
            int kb = l >> 7, j = l & 127;
            *(float4*)&Bs[kb][j] = cvt_tf32_4(*(const float4*)(Bm + (size_t)(k0 + kb) * Nn + colB + j));
        }
        __syncthreads();
        MMA_K8(As, Bs, 0)
        MMA_K8(As, Bs, 8)
        __syncthreads();
    }
    #pragma unroll
    for (int ma = 0; ma < 2; ma++) {
        int m0 = rowB + mW + ma * 16 + lr;
        float b0 = bo[m0], b1 = bo[m0 + 8];
        #pragma unroll
        for (int na = 0; na < 8; na++) {
            int cI = colB + nW + na * 8 + 2 * lc;
            size_t i0 = (size_t)(bb * Cc + m0) * Nn + cI;
            size_t i1 = (size_t)(bb * Cc + m0 + 8) * Nn + cI;
            float2 x0 = *(const float2*)(x + i0), x1 = *(const float2*)(x + i1);
            float2 v0 = {(x0.x + acc[ma][na][0] + b0) * RSQRT2f, (x0.y + acc[ma][na][1] + b0) * RSQRT2f};
            float2 v1 = {(x1.x + acc[ma][na][2] + b1) * RSQRT2f, (x1.y + acc[ma][na][3] + b1) * RSQRT2f};
            *(float2*)(out + i0) = v0;
            *(float2*)(out + i1) = v1;
        }
    }
}

// ---------------------------------------------------------------------------
extern "C" void kernel_launch(void* const* d_in, const int* in_sizes, int n_in,
                              void* d_out, int out_size) {
    const float* x  = (const float*)d_in[0];
    const float* gw = (const float*)d_in[1];
    const float* gb = (const float*)d_in[2];
    const float* Wq = (const float*)d_in[3];
    const float* bq = (const float*)d_in[4];
    const float* Wk = (const float*)d_in[5];
    const float* bk = (const float*)d_in[6];
    const float* Wv = (const float*)d_in[7];
    const float* bv = (const float*)d_in[8];
    const float* Wo = (const float*)d_in[9];
    const float* bo = (const float*)d_in[10];
    float* out = (float*)d_out;

    gn_kernel<<<Bn * 32, 256>>>(x, gw, gb);
    qkv_kernel<<<dim3(Nn / 128, Cc / 128, 12), 256>>>(Wq, bq, Wk, bk, Wv, bv);
    scores_bf_kernel<<<dim3(Nn / 128, Nn / 128, Bn), 256>>>();
    softmax_kernel<<<Bn * Nn, 256>>>();
    ao_bf_kernel<<<dim3(Nn / 128, Cc / 128, Bn), 256>>>();
    outproj_kernel<<<dim3(Nn / 128, Cc / 128, Bn), 256>>>(Wo, bo, x, out);
}

// round 7
// speedup vs baseline: 5.1530x; 1.4692x over previous
#include <cuda_runtime.h>
#include <cuda_fp16.h>
#include <cstdint>

#define Bn 4
#define Cc 256
#define Nn 4096
#define EPSf 1e-6f
#define RSQRT2f 0.70710678118654752440f
#define LOG2Ef 1.4426950408889634f
#define QSCALEf (0.0625f * LOG2Ef)

// fp16 tile geometry: 64-wide chunks, pitch 72 halfs (144 B) -> conflict-free LDSM
#define TP 144           // tile pitch bytes
#define TILE_B 18432     // 128 * 144
#define GSM (4 * TILE_B) // A0,A1,B0,B1 dynamic smem

// Scratch (device globals — allocation-free contract).
__device__ __half g_hst[Bn * Nn * Cc];              // GN out, transposed [B][N][C]
__device__ __half g_qh [Bn * Nn * Cc];              // Q^T [B][N][C], pre-scaled by QSCALE
__device__ __half g_kh [Bn * Nn * Cc];              // K^T [B][N][C]
__device__ __half g_vh [Bn * Cc * Nn];              // V [B][C][N]
__device__ float  g_p  [(size_t)Bn * Nn * Nn];      // scores fp32 (pre-softmax, log2-scaled)
__device__ __half g_ph [(size_t)Bn * Nn * Nn];      // probs fp16
__device__ __half g_aot[Bn * Nn * Cc];              // attn out transposed [B][N][C]

static __device__ __forceinline__ uint32_t smem_u32(const void* p) {
    uint32_t a;
    asm("{ .reg .u64 t; cvta.to.shared.u64 t, %1; cvt.u32.u64 %0, t; }" : "=r"(a) : "l"(p));
    return a;
}
#define LDSM4(r0, r1, r2, r3, addr)                                              \
    asm volatile("ldmatrix.sync.aligned.m8n8.x4.shared.b16 {%0,%1,%2,%3}, [%4];" \
                 : "=r"(r0), "=r"(r1), "=r"(r2), "=r"(r3) : "r"(addr))
#define MMA_F16(ac, a, b0, b1)                                                   \
    asm volatile("mma.sync.aligned.m16n8k16.row.col.f32.f16.f16.f32 "            \
                 "{%0,%1,%2,%3}, {%4,%5,%6,%7}, {%8,%9}, {%0,%1,%2,%3};"         \
                 : "+f"((ac)[0]), "+f"((ac)[1]), "+f"((ac)[2]), "+f"((ac)[3])    \
                 : "r"((a)[0]), "r"((a)[1]), "r"((a)[2]), "r"((a)[3]),           \
                   "r"(b0), "r"(b1))
#define CP_COMMIT() asm volatile("cp.async.commit_group;" ::: "memory")
#define CP_WAIT0()  asm volatile("cp.async.wait_group 0;" ::: "memory")

// cp.async a 128x64 fp16 tile (row-major src, stride STR halfs) into smem (pitch TP).
template <int STR>
static __device__ __forceinline__ void cp_tile(uint32_t dst, const __half* src,
                                               int r0, int k0, int tid) {
    #pragma unroll
    for (int p = 0; p < 4; p++) {
        int idx = tid + p * 256;
        int row = idx >> 3, seg = idx & 7;
        uint32_t d = dst + row * TP + seg * 16;
        const void* g = src + (size_t)(r0 + row) * STR + k0 + seg * 8;
        asm volatile("cp.async.ca.shared.global [%0], [%1], 16;" :: "r"(d), "l"(g));
    }
}

// Load 128x64 fp32 tile, convert to fp16, store to smem (pitch TP).
template <int STR>
static __device__ __forceinline__ void cvtA_tile(char* dst, const float* src,
                                                 int r0, int k0, int tid) {
    #pragma unroll
    for (int p = 0; p < 8; p++) {
        int idx = tid + p * 256;
        int row = idx >> 4, seg = idx & 15;
        float4 v = *(const float4*)(src + (size_t)(r0 + row) * STR + k0 + seg * 4);
        __half2 h0 = __floats2half2_rn(v.x, v.y);
        __half2 h1 = __floats2half2_rn(v.z, v.w);
        uint2 u = { *(uint32_t*)&h0, *(uint32_t*)&h1 };
        *(uint2*)(dst + row * TP + seg * 8) = u;
    }
}

// One 64-wide K chunk of fp16 mma for a 32(m) x 64(n) warp tile.
static __device__ __forceinline__ void compute64(uint32_t aBase, uint32_t bBase,
                                                 int lane, int mW, int nW,
                                                 float acc[2][8][4]) {
    #pragma unroll
    for (int ks = 0; ks < 4; ks++) {
        const int kb = ks * 32 + ((lane >> 4) << 4);
        uint32_t a[2][4];
        #pragma unroll
        for (int ma = 0; ma < 2; ma++) {
            uint32_t ad = aBase + (mW + ma * 16 + (lane & 15)) * TP + kb;
            LDSM4(a[ma][0], a[ma][1], a[ma][2], a[ma][3], ad);
        }
        #pragma unroll
        for (int nb = 0; nb < 4; nb++) {
            uint32_t b0, b1, b2, b3;
            uint32_t bd = bBase + (nW + nb * 16 + (lane & 15)) * TP + kb;
            LDSM4(b0, b1, b2, b3, bd);
            #pragma unroll
            for (int ma = 0; ma < 2; ma++) {
                MMA_F16(acc[ma][nb * 2 + 0], a[ma], b0, b2);
                MMA_F16(acc[ma][nb * 2 + 1], a[ma], b1, b3);
            }
        }
    }
}

// ---------------- GroupNorm: x [B][C][N] fp32 -> g_hst [B][N][C] fp16 ----------------
__global__ void __launch_bounds__(256) gn_kernel(const float* __restrict__ x,
                                                 const float* __restrict__ w,
                                                 const float* __restrict__ bgn) {
    const int bb = blockIdx.x >> 5, g = blockIdx.x & 31;
    const int GSIZE = 8 * Nn;
    const size_t base = (size_t)(bb * Cc + g * 8) * Nn;
    const float* xp = x + base;
    float s = 0.f, s2 = 0.f;
    for (int i = threadIdx.x; i < GSIZE; i += 256) { float v = xp[i]; s += v; s2 += v * v; }
    __shared__ float r1[8], r2[8], shm, shr;
    #pragma unroll
    for (int o = 16; o; o >>= 1) {
        s += __shfl_xor_sync(~0u, s, o); s2 += __shfl_xor_sync(~0u, s2, o);
    }
    if ((threadIdx.x & 31) == 0) { r1[threadIdx.x >> 5] = s; r2[threadIdx.x >> 5] = s2; }
    __syncthreads();
    if (threadIdx.x == 0) {
        s = 0.f; s2 = 0.f;
        #pragma unroll
        for (int i = 0; i < 8; i++) { s += r1[i]; s2 += r2[i]; }
        float mean = s / GSIZE, var = s2 / GSIZE - mean * mean;
        shm = mean; shr = rsqrtf(var + EPSf);
    }
    __syncthreads();
    const float mean = shm, rstd = shr;
    float wl[8], bl[8];
    #pragma unroll
    for (int c = 0; c < 8; c++) { wl[c] = w[g * 8 + c] * rstd; bl[c] = bgn[g * 8 + c]; }
    __half* hp = g_hst + (size_t)bb * Nn * Cc + g * 8;
    for (int n = threadIdx.x; n < Nn; n += 256) {
        __half h[8];
        #pragma unroll
        for (int c = 0; c < 8; c++)
            h[c] = __float2half((xp[(size_t)c * Nn + n] - mean) * wl[c] + bl[c]);
        *(uint4*)(hp + (size_t)n * Cc) = *(uint4*)h;
    }
}

// ---------------- QKV: M=cout(128), N=n(128), K=256. A=W(cvt), B=hst(cp) ----------------
__global__ void __launch_bounds__(256, 2) qkv_kernel(const float* __restrict__ Wq,
                                                     const float* __restrict__ bq,
                                                     const float* __restrict__ Wk,
                                                     const float* __restrict__ bk,
                                                     const float* __restrict__ Wv,
                                                     const float* __restrict__ bv) {
    extern __shared__ char sm[];
    const int z = blockIdx.z, which = z >> 2, bb = z & 3;
    const float* A; const float* bias;
    if (which == 0)      { A = Wq; bias = bq; }
    else if (which == 1) { A = Wk; bias = bk; }
    else                 { A = Wv; bias = bv; }
    const __half* Bm = g_hst + (size_t)bb * Nn * Cc;
    const int tid = threadIdx.x, lane = tid & 31, wid = tid >> 5;
    const int lr = lane >> 2, lc = lane & 3;
    const int mW = (wid & 3) * 32, nW = (wid >> 2) * 64;
    const int rowB = blockIdx.y * 128, colB = blockIdx.x * 128;
    float acc[2][8][4] = {};
    uint32_t sb = smem_u32(sm);
    uint32_t aB[2] = {sb, sb + TILE_B}, bB[2] = {sb + 2 * TILE_B, sb + 3 * TILE_B};

    cvtA_tile<Cc>(sm, A, rowB, 0, tid);
    cp_tile<Cc>(bB[0], Bm, colB, 0, tid);
    CP_COMMIT();
    #pragma unroll 1
    for (int c = 0; c < 4; c++) {
        CP_WAIT0();
        __syncthreads();
        if (c + 1 < 4) {
            cp_tile<Cc>(bB[(c + 1) & 1], Bm, colB, (c + 1) * 64, tid);
            CP_COMMIT();
            cvtA_tile<Cc>(sm + ((c + 1) & 1) * TILE_B, A, rowB, (c + 1) * 64, tid);
        }
        compute64(aB[c & 1], bB[c & 1], lane, mW, nW, acc);
    }
    const float fac = (which == 0) ? QSCALEf : 1.f;
    #pragma unroll
    for (int ma = 0; ma < 2; ma++) {
        int m0 = rowB + mW + ma * 16 + lr;
        float b0 = bias[m0], b1 = bias[m0 + 8];
        #pragma unroll
        for (int idx = 0; idx < 8; idx++) {
            int cI = colB + nW + (idx >> 1) * 16 + (idx & 1) * 8 + 2 * lc;
            if (which < 2) {
                __half* Cb = (which == 0 ? g_qh : g_kh) + (size_t)bb * Nn * Cc;
                Cb[(size_t)cI * Cc + m0]           = __float2half((acc[ma][idx][0] + b0) * fac);
                Cb[(size_t)(cI + 1) * Cc + m0]     = __float2half((acc[ma][idx][1] + b0) * fac);
                Cb[(size_t)cI * Cc + m0 + 8]       = __float2half((acc[ma][idx][2] + b1) * fac);
                Cb[(size_t)(cI + 1) * Cc + m0 + 8] = __float2half((acc[ma][idx][3] + b1) * fac);
            } else {
                __half* Cb = g_vh + (size_t)bb * Cc * Nn;
                __half2 p0 = __floats2half2_rn(acc[ma][idx][0] + b0, acc[ma][idx][1] + b0);
                __half2 p1 = __floats2half2_rn(acc[ma][idx][2] + b1, acc[ma][idx][3] + b1);
                *(__half2*)(Cb + (size_t)m0 * Nn + cI)       = p0;
                *(__half2*)(Cb + (size_t)(m0 + 8) * Nn + cI) = p1;
            }
        }
    }
}

// ---------------- scores: S = Q'^T K  (both [N][C] fp16, TN), M=128 N=128 K=256 ----------------
__global__ void __launch_bounds__(256, 2) scores_kernel() {
    extern __shared__ char sm[];
    const int tid = threadIdx.x, lane = tid & 31, wid = tid >> 5;
    const int lr = lane >> 2, lc = lane & 3;
    const int mW = (wid & 3) * 32, nW = (wid >> 2) * 64;
    const int bb = blockIdx.z, rowB = blockIdx.y * 128, colB = blockIdx.x * 128;
    const __half* Qt = g_qh + (size_t)bb * Nn * Cc;
    const __half* Kt = g_kh + (size_t)bb * Nn * Cc;
    float* S = g_p + (size_t)bb * Nn * Nn;
    float acc[2][8][4] = {};
    uint32_t sb = smem_u32(sm);
    uint32_t aB[2] = {sb, sb + TILE_B}, bB[2] = {sb + 2 * TILE_B, sb + 3 * TILE_B};

    cp_tile<Cc>(aB[0], Qt, rowB, 0, tid);
    cp_tile<Cc>(bB[0], Kt, colB, 0, tid);
    CP_COMMIT();
    #pragma unroll 1
    for (int c = 0; c < 4; c++) {
        CP_WAIT0();
        __syncthreads();
        if (c + 1 < 4) {
            cp_tile<Cc>(aB[(c + 1) & 1], Qt, rowB, (c + 1) * 64, tid);
            cp_tile<Cc>(bB[(c + 1) & 1], Kt, colB, (c + 1) * 64, tid);
            CP_COMMIT();
        }
        compute64(aB[c & 1], bB[c & 1], lane, mW, nW, acc);
    }
    #pragma unroll
    for (int ma = 0; ma < 2; ma++) {
        int m0 = rowB + mW + ma * 16 + lr;
        #pragma unroll
        for (int idx = 0; idx < 8; idx++) {
            int cI = colB + nW + (idx >> 1) * 16 + (idx & 1) * 8 + 2 * lc;
            float2 v0 = {acc[ma][idx][0], acc[ma][idx][1]};
            float2 v1 = {acc[ma][idx][2], acc[ma][idx][3]};
            *(float2*)(S + (size_t)m0 * Nn + cI)       = v0;
            *(float2*)(S + (size_t)(m0 + 8) * Nn + cI) = v1;
        }
    }
}

// ---------------- softmax: S fp32 (log2-domain) -> P fp16 via ex2.f16x2 ----------------
__global__ void __launch_bounds__(256) softmax_kernel() {
    __shared__ float buf[Nn];
    __shared__ __half2 pbuf[Nn / 2];
    __shared__ float red[8];
    const float* p = g_p + (size_t)blockIdx.x * Nn;
    __half2* pb = (__half2*)(g_ph + (size_t)blockIdx.x * Nn);
    const int tid = threadIdx.x;

    float m = -3.4e38f;
    #pragma unroll
    for (int it = 0; it < 4; it++) {
        int i = tid + it * 256;
        float4 v = *(const float4*)(p + i * 4);
        *(float4*)(buf + i * 4) = v;
        m = fmaxf(fmaxf(fmaxf(m, v.x), fmaxf(v.y, v.z)), v.w);
    }
    #pragma unroll
    for (int o = 16; o; o >>= 1) m = fmaxf(m, __shfl_xor_sync(~0u, m, o));
    if ((tid & 31) == 0) red[tid >> 5] = m;
    __syncthreads();
    if (tid < 8) {
        m = red[tid];
        #pragma unroll
        for (int o = 4; o; o >>= 1) m = fmaxf(m, __shfl_xor_sync(0xffu, m, o));
        if (tid == 0) red[0] = m;
    }
    __syncthreads();
    m = red[0];
    __syncthreads();

    float sum = 0.f;
    #pragma unroll
    for (int it = 0; it < 8; it++) {
        int i = tid * 2 + it * 512;
        __half2 e = h2exp2(__floats2half2_rn(buf[i] - m, buf[i + 1] - m));
        pbuf[tid + it * 256] = e;
        float2 f = __half22float2(e);
        sum += f.x + f.y;
    }
    #pragma unroll
    for (int o = 16; o; o >>= 1) sum += __shfl_xor_sync(~0u, sum, o);
    if ((tid & 31) == 0) red[tid >> 5] = sum;
    __syncthreads();
    if (tid < 8) {
        sum = red[tid];
        #pragma unroll
        for (int o = 4; o; o >>= 1) sum += __shfl_xor_sync(0xffu, sum, o);
        if (tid == 0) red[0] = sum;
    }
    __syncthreads();
    const __half2 inv = __float2half2_rn(1.f / red[0]);
    for (int i = tid; i < Nn / 2; i += 256) pb[i] = __hmul2(pbuf[i], inv);
}

// ---------------- ao: AO[c][n] = sum_j V[c][j] P[n][j] -> g_aot [N][C] fp16 ----------------
__global__ void __launch_bounds__(256, 2) ao_kernel() {
    extern __shared__ char sm[];
    const int tid = threadIdx.x, lane = tid & 31, wid = tid >> 5;
    const int lr = lane >> 2, lc = lane & 3;
    const int mW = (wid & 3) * 32, nW = (wid >> 2) * 64;
    const int bb = blockIdx.z, rowB = blockIdx.y * 128, colB = blockIdx.x * 128;
    const __half* Vh = g_vh + (size_t)bb * Cc * Nn;
    const __half* Ph = g_ph + (size_t)bb * Nn * Nn;
    __half* AOt = g_aot + (size_t)bb * Nn * Cc;
    float acc[2][8][4] = {};
    uint32_t sb = smem_u32(sm);
    uint32_t aB[2] = {sb, sb + TILE_B}, bB[2] = {sb + 2 * TILE_B, sb + 3 * TILE_B};

    cp_tile<Nn>(aB[0], Vh, rowB, 0, tid);
    cp_tile<Nn>(bB[0], Ph, colB, 0, tid);
    CP_COMMIT();
    #pragma unroll 1
    for (int c = 0; c < 64; c++) {
        CP_WAIT0();
        __syncthreads();
        if (c + 1 < 64) {
            cp_tile<Nn>(aB[(c + 1) & 1], Vh, rowB, (c + 1) * 64, tid);
            cp_tile<Nn>(bB[(c + 1) & 1], Ph, colB, (c + 1) * 64, tid);
            CP_COMMIT();
        }
        compute64(aB[c & 1], bB[c & 1], lane, mW, nW, acc);
    }
    #pragma unroll
    for (int ma = 0; ma < 2; ma++) {
        int m0 = rowB + mW + ma * 16 + lr;   // channel c
        #pragma unroll
        for (int idx = 0; idx < 8; idx++) {
            int cI = colB + nW + (idx >> 1) * 16 + (idx & 1) * 8 + 2 * lc;  // spatial n
            AOt[(size_t)cI * Cc + m0]           = __float2half(acc[ma][idx][0]);
            AOt[(size_t)(cI + 1) * Cc + m0]     = __float2half(acc[ma][idx][1]);
            AOt[(size_t)cI * Cc + m0 + 8]       = __float2half(acc[ma][idx][2]);
            AOt[(size_t)(cI + 1) * Cc + m0 + 8] = __float2half(acc[ma][idx][3]);
        }
    }
}

// ---------------- outproj: out = Wo * AO + bo, residual. A=Wo(cvt), B=AOt(cp) ----------------
__global__ void __launch_bounds__(256, 2) outproj_kernel(const float* __restrict__ Wo,
                                                         const float* __restrict__ bo,
                                                         const float* __restrict__ x,
                                                         float* __restrict__ out) {
    extern __shared__ char sm[];
    const int tid = threadIdx.x, lane = tid & 31, wid = tid >> 5;
    const int lr = lane >> 2, lc = lane & 3;
    const int mW = (wid & 3) * 32, nW = (wid >> 2) * 64;
    const int bb = blockIdx.z, rowB = blockIdx.y * 128, colB = blockIdx.x * 128;
    const __half* Bm = g_aot + (size_t)bb * Nn * Cc;
    float acc[2][8][4] = {};
    uint32_t sb = smem_u32(sm);
    uint32_t aB[2] = {sb, sb + TILE_B}, bB[2] = {sb + 2 * TILE_B, sb + 3 * TILE_B};

    cvtA_tile<Cc>(sm, Wo, rowB, 0, tid);
    cp_tile<Cc>(bB[0], Bm, colB, 0, tid);
    CP_COMMIT();
    #pragma unroll 1
    for (int c = 0; c < 4; c++) {
        CP_WAIT0();
        __syncthreads();
        if (c + 1 < 4) {
            cp_tile<Cc>(bB[(c + 1) & 1], Bm, colB, (c + 1) * 64, tid);
            CP_COMMIT();
            cvtA_tile<Cc>(sm + ((c + 1) & 1) * TILE_B, Wo, rowB, (c + 1) * 64, tid);
        }
        compute64(aB[c & 1], bB[c & 1], lane, mW, nW, acc);
    }
    #pragma unroll
    for (int ma = 0; ma < 2; ma++) {
        int m0 = rowB + mW + ma * 16 + lr;
        float b0 = bo[m0], b1 = bo[m0 + 8];
        #pragma unroll
        for (int idx = 0; idx < 8; idx++) {
            int cI = colB + nW + (idx >> 1) * 16 + (idx & 1) * 8 + 2 * lc;
            size_t i0 = (size_t)(bb * Cc + m0) * Nn + cI;
            size_t i1 = (size_t)(bb * Cc + m0 + 8) * Nn + cI;
            float2 x0 = *(const float2*)(x + i0), x1 = *(const float2*)(x + i1);
            float2 v0 = {(x0.x + acc[ma][idx][0] + b0) * RSQRT2f,
                         (x0.y + acc[ma][idx][1] + b0) * RSQRT2f};
            float2 v1 = {(x1.x + acc[ma][idx][2] + b1) * RSQRT2f,
                         (x1.y + acc[ma][idx][3] + b1) * RSQRT2f};
            *(float2*)(out + i0) = v0;
            *(float2*)(out + i1) = v1;
        }
    }
}

// ---------------------------------------------------------------------------
extern "C" void kernel_launch(void* const* d_in, const int* in_sizes, int n_in,
                              void* d_out, int out_size) {
    const float* x  = (const float*)d_in[0];
    const float* gw = (const float*)d_in[1];
    const float* gb = (const float*)d_in[2];
    const float* Wq = (const float*)d_in[3];
    const float* bq = (const float*)d_in[4];
    const float* Wk = (const float*)d_in[5];
    const float* bk = (const float*)d_in[6];
    const float* Wv = (const float*)d_in[7];
    const float* bv = (const float*)d_in[8];
    const float* Wo = (const float*)d_in[9];
    const float* bo = (const float*)d_in[10];
    float* out = (float*)d_out;

    static bool attr_done = false;
    if (!attr_done) {
        cudaFuncSetAttribute(qkv_kernel,     cudaFuncAttributeMaxDynamicSharedMemorySize, GSM);
        cudaFuncSetAttribute(scores_kernel,  cudaFuncAttributeMaxDynamicSharedMemorySize, GSM);
        cudaFuncSetAttribute(ao_kernel,      cudaFuncAttributeMaxDynamicSharedMemorySize, GSM);
        cudaFuncSetAttribute(outproj_kernel, cudaFuncAttributeMaxDynamicSharedMemorySize, GSM);
        attr_done = true;
    }

    gn_kernel<<<Bn * 32, 256>>>(x, gw, gb);
    qkv_kernel<<<dim3(Nn / 128, Cc / 128, 12), 256, GSM>>>(Wq, bq, Wk, bk, Wv, bv);
    scores_kernel<<<dim3(Nn / 128, Nn / 128, Bn), 256, GSM>>>();
    softmax_kernel<<<Bn * Nn, 256>>>();
    ao_kernel<<<dim3(Nn / 128, Cc / 128, Bn), 256, GSM>>>();
    outproj_kernel<<<dim3(Nn / 128, Cc / 128, Bn), 256, GSM>>>(Wo, bo, x, out);
}

// round 8
// speedup vs baseline: 5.6696x; 1.1003x over previous
#include <cuda_runtime.h>
#include <cuda_fp16.h>
#include <cstdint>

#define Bn 4
#define Cc 256
#define Nn 4096
#define EPSf 1e-6f
#define RSQRT2f 0.70710678118654752440f
#define LOG2Ef 1.4426950408889634f
#define QSCALEf (0.0625f * LOG2Ef)

// fp16 tile geometry: 64-wide chunks, pitch 72 halfs (144 B) -> conflict-free LDSM
#define TP 144           // tile pitch bytes
#define TILE_B 18432     // 128 * 144
#define GSM (4 * TILE_B) // A0,A1,B0,B1 dynamic smem

// Scratch (device globals — allocation-free contract).
__device__ __half g_hst[Bn * Nn * Cc];              // GN out, transposed [B][N][C]
__device__ __half g_qh [Bn * Nn * Cc];              // Q^T [B][N][C], pre-scaled by QSCALE
__device__ __half g_kh [Bn * Nn * Cc];              // K^T [B][N][C]
__device__ __half g_vh [Bn * Cc * Nn];              // V [B][C][N]
__device__ __half g_p  [(size_t)Bn * Nn * Nn];      // scores fp16 (pre-softmax, log2-scaled)
__device__ __half g_ph [(size_t)Bn * Nn * Nn];      // probs fp16
__device__ __half g_aot[Bn * Nn * Cc];              // attn out transposed [B][N][C]

static __device__ __forceinline__ uint32_t smem_u32(const void* p) {
    uint32_t a;
    asm("{ .reg .u64 t; cvta.to.shared.u64 t, %1; cvt.u32.u64 %0, t; }" : "=r"(a) : "l"(p));
    return a;
}
#define LDSM4(r0, r1, r2, r3, addr)                                              \
    asm volatile("ldmatrix.sync.aligned.m8n8.x4.shared.b16 {%0,%1,%2,%3}, [%4];" \
                 : "=r"(r0), "=r"(r1), "=r"(r2), "=r"(r3) : "r"(addr))
#define MMA_F16(ac, a, b0, b1)                                                   \
    asm volatile("mma.sync.aligned.m16n8k16.row.col.f32.f16.f16.f32 "            \
                 "{%0,%1,%2,%3}, {%4,%5,%6,%7}, {%8,%9}, {%0,%1,%2,%3};"         \
                 : "+f"((ac)[0]), "+f"((ac)[1]), "+f"((ac)[2]), "+f"((ac)[3])    \
                 : "r"((a)[0]), "r"((a)[1]), "r"((a)[2]), "r"((a)[3]),           \
                   "r"(b0), "r"(b1))
#define CP_COMMIT() asm volatile("cp.async.commit_group;" ::: "memory")
#define CP_WAIT0()  asm volatile("cp.async.wait_group 0;" ::: "memory")

// cp.async a 128x64 fp16 tile (row-major src, stride STR halfs) into smem (pitch TP).
template <int STR>
static __device__ __forceinline__ void cp_tile(uint32_t dst, const __half* src,
                                               int r0, int k0, int tid) {
    #pragma unroll
    for (int p = 0; p < 4; p++) {
        int idx = tid + p * 256;
        int row = idx >> 3, seg = idx & 7;
        uint32_t d = dst + row * TP + seg * 16;
        const void* g = src + (size_t)(r0 + row) * STR + k0 + seg * 8;
        asm volatile("cp.async.ca.shared.global [%0], [%1], 16;" :: "r"(d), "l"(g));
    }
}

// Load 128x64 fp32 tile, convert to fp16, store to smem (pitch TP).
template <int STR>
static __device__ __forceinline__ void cvtA_tile(char* dst, const float* src,
                                                 int r0, int k0, int tid) {
    #pragma unroll
    for (int p = 0; p < 8; p++) {
        int idx = tid + p * 256;
        int row = idx >> 4, seg = idx & 15;
        float4 v = *(const float4*)(src + (size_t)(r0 + row) * STR + k0 + seg * 4);
        __half2 h0 = __floats2half2_rn(v.x, v.y);
        __half2 h1 = __floats2half2_rn(v.z, v.w);
        uint2 u = { *(uint32_t*)&h0, *(uint32_t*)&h1 };
        *(uint2*)(dst + row * TP + seg * 8) = u;
    }
}

// One 64-wide K chunk of fp16 mma for a 32(m) x 64(n) warp tile.
static __device__ __forceinline__ void compute64(uint32_t aBase, uint32_t bBase,
                                                 int lane, int mW, int nW,
                                                 float acc[2][8][4]) {
    #pragma unroll
    for (int ks = 0; ks < 4; ks++) {
        const int kb = ks * 32 + ((lane >> 4) << 4);
        uint32_t a[2][4];
        #pragma unroll
        for (int ma = 0; ma < 2; ma++) {
            uint32_t ad = aBase + (mW + ma * 16 + (lane & 15)) * TP + kb;
            LDSM4(a[ma][0], a[ma][1], a[ma][2], a[ma][3], ad);
        }
        #pragma unroll
        for (int nb = 0; nb < 4; nb++) {
            uint32_t b0, b1, b2, b3;
            uint32_t bd = bBase + (nW + nb * 16 + (lane & 15)) * TP + kb;
            LDSM4(b0, b1, b2, b3, bd);
            #pragma unroll
            for (int ma = 0; ma < 2; ma++) {
                MMA_F16(acc[ma][nb * 2 + 0], a[ma], b0, b2);
                MMA_F16(acc[ma][nb * 2 + 1], a[ma], b1, b3);
            }
        }
    }
}

// ---------------- GroupNorm: x [B][C][N] fp32 -> g_hst [B][N][C] fp16 ----------------
__global__ void __launch_bounds__(256) gn_kernel(const float* __restrict__ x,
                                                 const float* __restrict__ w,
                                                 const float* __restrict__ bgn) {
    const int bb = blockIdx.x >> 5, g = blockIdx.x & 31;
    const int GSIZE = 8 * Nn;
    const size_t base = (size_t)(bb * Cc + g * 8) * Nn;
    const float* xp = x + base;
    float s = 0.f, s2 = 0.f;
    for (int i = threadIdx.x; i < GSIZE; i += 256) { float v = xp[i]; s += v; s2 += v * v; }
    __shared__ float r1[8], r2[8], shm, shr;
    #pragma unroll
    for (int o = 16; o; o >>= 1) {
        s += __shfl_xor_sync(~0u, s, o); s2 += __shfl_xor_sync(~0u, s2, o);
    }
    if ((threadIdx.x & 31) == 0) { r1[threadIdx.x >> 5] = s; r2[threadIdx.x >> 5] = s2; }
    __syncthreads();
    if (threadIdx.x == 0) {
        s = 0.f; s2 = 0.f;
        #pragma unroll
        for (int i = 0; i < 8; i++) { s += r1[i]; s2 += r2[i]; }
        float mean = s / GSIZE, var = s2 / GSIZE - mean * mean;
        shm = mean; shr = rsqrtf(var + EPSf);
    }
    __syncthreads();
    const float mean = shm, rstd = shr;
    float wl[8], bl[8];
    #pragma unroll
    for (int c = 0; c < 8; c++) { wl[c] = w[g * 8 + c] * rstd; bl[c] = bgn[g * 8 + c]; }
    __half* hp = g_hst + (size_t)bb * Nn * Cc + g * 8;
    for (int n = threadIdx.x; n < Nn; n += 256) {
        __half h[8];
        #pragma unroll
        for (int c = 0; c < 8; c++)
            h[c] = __float2half((xp[(size_t)c * Nn + n] - mean) * wl[c] + bl[c]);
        *(uint4*)(hp + (size_t)n * Cc) = *(uint4*)h;
    }
}

// ---------------- QKV: M=cout(128), N=n(128), K=256. A=W(cvt), B=hst(cp) ----------------
__global__ void __launch_bounds__(256, 2) qkv_kernel(const float* __restrict__ Wq,
                                                     const float* __restrict__ bq,
                                                     const float* __restrict__ Wk,
                                                     const float* __restrict__ bk,
                                                     const float* __restrict__ Wv,
                                                     const float* __restrict__ bv) {
    extern __shared__ char sm[];
    const int z = blockIdx.z, which = z >> 2, bb = z & 3;
    const float* A; const float* bias;
    if (which == 0)      { A = Wq; bias = bq; }
    else if (which == 1) { A = Wk; bias = bk; }
    else                 { A = Wv; bias = bv; }
    const __half* Bm = g_hst + (size_t)bb * Nn * Cc;
    const int tid = threadIdx.x, lane = tid & 31, wid = tid >> 5;
    const int lr = lane >> 2, lc = lane & 3;
    const int mW = (wid & 3) * 32, nW = (wid >> 2) * 64;
    const int rowB = blockIdx.y * 128, colB = blockIdx.x * 128;
    float acc[2][8][4] = {};
    uint32_t sb = smem_u32(sm);
    uint32_t aB[2] = {sb, sb + TILE_B}, bB[2] = {sb + 2 * TILE_B, sb + 3 * TILE_B};

    cvtA_tile<Cc>(sm, A, rowB, 0, tid);
    cp_tile<Cc>(bB[0], Bm, colB, 0, tid);
    CP_COMMIT();
    #pragma unroll 1
    for (int c = 0; c < 4; c++) {
        CP_WAIT0();
        __syncthreads();
        if (c + 1 < 4) {
            cp_tile<Cc>(bB[(c + 1) & 1], Bm, colB, (c + 1) * 64, tid);
            CP_COMMIT();
            cvtA_tile<Cc>(sm + ((c + 1) & 1) * TILE_B, A, rowB, (c + 1) * 64, tid);
        }
        compute64(aB[c & 1], bB[c & 1], lane, mW, nW, acc);
    }
    const float fac = (which == 0) ? QSCALEf : 1.f;
    #pragma unroll
    for (int ma = 0; ma < 2; ma++) {
        int m0 = rowB + mW + ma * 16 + lr;
        float b0 = bias[m0], b1 = bias[m0 + 8];
        #pragma unroll
        for (int idx = 0; idx < 8; idx++) {
            int cI = colB + nW + (idx >> 1) * 16 + (idx & 1) * 8 + 2 * lc;
            if (which < 2) {
                __half* Cb = (which == 0 ? g_qh : g_kh) + (size_t)bb * Nn * Cc;
                Cb[(size_t)cI * Cc + m0]           = __float2half((acc[ma][idx][0] + b0) * fac);
                Cb[(size_t)(cI + 1) * Cc + m0]     = __float2half((acc[ma][idx][1] + b0) * fac);
                Cb[(size_t)cI * Cc + m0 + 8]       = __float2half((acc[ma][idx][2] + b1) * fac);
                Cb[(size_t)(cI + 1) * Cc + m0 + 8] = __float2half((acc[ma][idx][3] + b1) * fac);
            } else {
                __half* Cb = g_vh + (size_t)bb * Cc * Nn;
                __half2 p0 = __floats2half2_rn(acc[ma][idx][0] + b0, acc[ma][idx][1] + b0);
                __half2 p1 = __floats2half2_rn(acc[ma][idx][2] + b1, acc[ma][idx][3] + b1);
                *(__half2*)(Cb + (size_t)m0 * Nn + cI)       = p0;
                *(__half2*)(Cb + (size_t)(m0 + 8) * Nn + cI) = p1;
            }
        }
    }
}

// ---------------- scores: S = Q'^T K  -> fp16 (log2-scaled), M=128 N=128 K=256 ----------------
__global__ void __launch_bounds__(256, 2) scores_kernel() {
    extern __shared__ char sm[];
    const int tid = threadIdx.x, lane = tid & 31, wid = tid >> 5;
    const int lr = lane >> 2, lc = lane & 3;
    const int mW = (wid & 3) * 32, nW = (wid >> 2) * 64;
    const int bb = blockIdx.z, rowB = blockIdx.y * 128, colB = blockIdx.x * 128;
    const __half* Qt = g_qh + (size_t)bb * Nn * Cc;
    const __half* Kt = g_kh + (size_t)bb * Nn * Cc;
    __half* S = g_p + (size_t)bb * Nn * Nn;
    float acc[2][8][4] = {};
    uint32_t sb = smem_u32(sm);
    uint32_t aB[2] = {sb, sb + TILE_B}, bB[2] = {sb + 2 * TILE_B, sb + 3 * TILE_B};

    cp_tile<Cc>(aB[0], Qt, rowB, 0, tid);
    cp_tile<Cc>(bB[0], Kt, colB, 0, tid);
    CP_COMMIT();
    #pragma unroll 1
    for (int c = 0; c < 4; c++) {
        CP_WAIT0();
        __syncthreads();
        if (c + 1 < 4) {
            cp_tile<Cc>(aB[(c + 1) & 1], Qt, rowB, (c + 1) * 64, tid);
            cp_tile<Cc>(bB[(c + 1) & 1], Kt, colB, (c + 1) * 64, tid);
            CP_COMMIT();
        }
        compute64(aB[c & 1], bB[c & 1], lane, mW, nW, acc);
    }
    #pragma unroll
    for (int ma = 0; ma < 2; ma++) {
        int m0 = rowB + mW + ma * 16 + lr;
        #pragma unroll
        for (int idx = 0; idx < 8; idx++) {
            int cI = colB + nW + (idx >> 1) * 16 + (idx & 1) * 8 + 2 * lc;
            __half2 v0 = __floats2half2_rn(acc[ma][idx][0], acc[ma][idx][1]);
            __half2 v1 = __floats2half2_rn(acc[ma][idx][2], acc[ma][idx][3]);
            *(__half2*)(S + (size_t)m0 * Nn + cI)       = v0;
            *(__half2*)(S + (size_t)(m0 + 8) * Nn + cI) = v1;
        }
    }
}

// ---------------- softmax: S fp16 (log2-domain) -> P fp16 via ex2.f16x2 ----------------
__global__ void __launch_bounds__(256) softmax_kernel() {
    __shared__ __half2 buf[Nn / 2];
    __shared__ float red[8];
    const uint4* p = (const uint4*)(g_p + (size_t)blockIdx.x * Nn);
    uint4* pb = (uint4*)(g_ph + (size_t)blockIdx.x * Nn);
    const int tid = threadIdx.x;

    // pass 1: load S (8 halfs/thread/iter), cache in smem, row max
    float m = -3.4e38f;
    #pragma unroll
    for (int it = 0; it < 2; it++) {
        int i = tid + it * 256;
        uint4 v = p[i];
        *(uint4*)(buf + i * 4) = v;
        __half2 h0 = *(__half2*)&v.x, h1 = *(__half2*)&v.y;
        __half2 h2 = *(__half2*)&v.z, h3 = *(__half2*)&v.w;
        __half2 mx = __hmax2(__hmax2(h0, h1), __hmax2(h2, h3));
        m = fmaxf(m, fmaxf(__low2float(mx), __high2float(mx)));
    }
    #pragma unroll
    for (int o = 16; o; o >>= 1) m = fmaxf(m, __shfl_xor_sync(~0u, m, o));
    if ((tid & 31) == 0) red[tid >> 5] = m;
    __syncthreads();
    if (tid < 8) {
        m = red[tid];
        #pragma unroll
        for (int o = 4; o; o >>= 1) m = fmaxf(m, __shfl_xor_sync(0xffu, m, o));
        if (tid == 0) red[0] = m;
    }
    __syncthreads();
    const __half2 m2 = __float2half2_rn(red[0]);
    __syncthreads();

    // pass 2: exp2 in fp16x2, overwrite smem, accumulate sum in fp32
    float sum = 0.f;
    #pragma unroll
    for (int it = 0; it < 8; it++) {
        int i = tid + it * 256;
        __half2 e = h2exp2(__hsub2(buf[i], m2));
        buf[i] = e;
        float2 f = __half22float2(e);
        sum += f.x + f.y;
    }
    #pragma unroll
    for (int o = 16; o; o >>= 1) sum += __shfl_xor_sync(~0u, sum, o);
    if ((tid & 31) == 0) red[tid >> 5] = sum;
    __syncthreads();
    if (tid < 8) {
        sum = red[tid];
        #pragma unroll
        for (int o = 4; o; o >>= 1) sum += __shfl_xor_sync(0xffu, sum, o);
        if (tid == 0) red[0] = sum;
    }
    __syncthreads();
    const __half2 inv = __float2half2_rn(1.f / red[0]);

    // pass 3: normalize + write P (8 halfs/thread/iter)
    #pragma unroll
    for (int it = 0; it < 2; it++) {
        int i = tid + it * 256;
        __half2 e0 = __hmul2(buf[i * 4 + 0], inv);
        __half2 e1 = __hmul2(buf[i * 4 + 1], inv);
        __half2 e2 = __hmul2(buf[i * 4 + 2], inv);
        __half2 e3 = __hmul2(buf[i * 4 + 3], inv);
        uint4 v = { *(uint32_t*)&e0, *(uint32_t*)&e1, *(uint32_t*)&e2, *(uint32_t*)&e3 };
        pb[i] = v;
    }
}

// ---------------- ao: AO[c][n] = sum_j V[c][j] P[n][j] -> g_aot [N][C] fp16 ----------------
__global__ void __launch_bounds__(256, 2) ao_kernel() {
    extern __shared__ char sm[];
    const int tid = threadIdx.x, lane = tid & 31, wid = tid >> 5;
    const int lr = lane >> 2, lc = lane & 3;
    const int mW = (wid & 3) * 32, nW = (wid >> 2) * 64;
    const int bb = blockIdx.z, rowB = blockIdx.y * 128, colB = blockIdx.x * 128;
    const __half* Vh = g_vh + (size_t)bb * Cc * Nn;
    const __half* Ph = g_ph + (size_t)bb * Nn * Nn;
    __half* AOt = g_aot + (size_t)bb * Nn * Cc;
    float acc[2][8][4] = {};
    uint32_t sb = smem_u32(sm);
    uint32_t aB[2] = {sb, sb + TILE_B}, bB[2] = {sb + 2 * TILE_B, sb + 3 * TILE_B};

    cp_tile<Nn>(aB[0], Vh, rowB, 0, tid);
    cp_tile<Nn>(bB[0], Ph, colB, 0, tid);
    CP_COMMIT();
    #pragma unroll 1
    for (int c = 0; c < 64; c++) {
        CP_WAIT0();
        __syncthreads();
        if (c + 1 < 64) {
            cp_tile<Nn>(aB[(c + 1) & 1], Vh, rowB, (c + 1) * 64, tid);
            cp_tile<Nn>(bB[(c + 1) & 1], Ph, colB, (c + 1) * 64, tid);
            CP_COMMIT();
        }
        compute64(aB[c & 1], bB[c & 1], lane, mW, nW, acc);
    }
    #pragma unroll
    for (int ma = 0; ma < 2; ma++) {
        int m0 = rowB + mW + ma * 16 + lr;   // channel c
        #pragma unroll
        for (int idx = 0; idx < 8; idx++) {
            int cI = colB + nW + (idx >> 1) * 16 + (idx & 1) * 8 + 2 * lc;  // spatial n
            AOt[(size_t)cI * Cc + m0]           = __float2half(acc[ma][idx][0]);
            AOt[(size_t)(cI + 1) * Cc + m0]     = __float2half(acc[ma][idx][1]);
            AOt[(size_t)cI * Cc + m0 + 8]       = __float2half(acc[ma][idx][2]);
            AOt[(size_t)(cI + 1) * Cc + m0 + 8] = __float2half(acc[ma][idx][3]);
        }
    }
}

// ---------------- outproj: out = Wo * AO + bo, residual. A=Wo(cvt), B=AOt(cp) ----------------
__global__ void __launch_bounds__(256, 2) outproj_kernel(const float* __restrict__ Wo,
                                                         const float* __restrict__ bo,
                                                         const float* __restrict__ x,
                                                         float* __restrict__ out) {
    extern __shared__ char sm[];
    const int tid = threadIdx.x, lane = tid & 31, wid = tid >> 5;
    const int lr = lane >> 2, lc = lane & 3;
    const int mW = (wid & 3) * 32, nW = (wid >> 2) * 64;
    const int bb = blockIdx.z, rowB = blockIdx.y * 128, colB = blockIdx.x * 128;
    const __half* Bm = g_aot + (size_t)bb * Nn * Cc;
    float acc[2][8][4] = {};
    uint32_t sb = smem_u32(sm);
    uint32_t aB[2] = {sb, sb + TILE_B}, bB[2] = {sb + 2 * TILE_B, sb + 3 * TILE_B};

    cvtA_tile<Cc>(sm, Wo, rowB, 0, tid);
    cp_tile<Cc>(bB[0], Bm, colB, 0, tid);
    CP_COMMIT();
    #pragma unroll 1
    for (int c = 0; c < 4; c++) {
        CP_WAIT0();
        __syncthreads();
        if (c + 1 < 4) {
            cp_tile<Cc>(bB[(c + 1) & 1], Bm, colB, (c + 1) * 64, tid);
            CP_COMMIT();
            cvtA_tile<Cc>(sm + ((c + 1) & 1) * TILE_B, Wo, rowB, (c + 1) * 64, tid);
        }
        compute64(aB[c & 1], bB[c & 1], lane, mW, nW, acc);
    }
    #pragma unroll
    for (int ma = 0; ma < 2; ma++) {
        int m0 = rowB + mW + ma * 16 + lr;
        float b0 = bo[m0], b1 = bo[m0 + 8];
        #pragma unroll
        for (int idx = 0; idx < 8; idx++) {
            int cI = colB + nW + (idx >> 1) * 16 + (idx & 1) * 8 + 2 * lc;
            size_t i0 = (size_t)(bb * Cc + m0) * Nn + cI;
            size_t i1 = (size_t)(bb * Cc + m0 + 8) * Nn + cI;
            float2 x0 = *(const float2*)(x + i0), x1 = *(const float2*)(x + i1);
            float2 v0 = {(x0.x + acc[ma][idx][0] + b0) * RSQRT2f,
                         (x0.y + acc[ma][idx][1] + b0) * RSQRT2f};
            float2 v1 = {(x1.x + acc[ma][idx][2] + b1) * RSQRT2f,
                         (x1.y + acc[ma][idx][3] + b1) * RSQRT2f};
            *(float2*)(out + i0) = v0;
            *(float2*)(out + i1) = v1;
        }
    }
}

// ---------------------------------------------------------------------------
extern "C" void kernel_launch(void* const* d_in, const int* in_sizes, int n_in,
                              void* d_out, int out_size) {
    const float* x  = (const float*)d_in[0];
    const float* gw = (const float*)d_in[1];
    const float* gb = (const float*)d_in[2];
    const float* Wq = (const float*)d_in[3];
    const float* bq = (const float*)d_in[4];
    const float* Wk = (const float*)d_in[5];
    const float* bk = (const float*)d_in[6];
    const float* Wv = (const float*)d_in[7];
    const float* bv = (const float*)d_in[8];
    const float* Wo = (const float*)d_in[9];
    const float* bo = (const float*)d_in[10];
    float* out = (float*)d_out;

    static bool attr_done = false;
    if (!attr_done) {
        cudaFuncSetAttribute(qkv_kernel,     cudaFuncAttributeMaxDynamicSharedMemorySize, GSM);
        cudaFuncSetAttribute(scores_kernel,  cudaFuncAttributeMaxDynamicSharedMemorySize, GSM);
        cudaFuncSetAttribute(ao_kernel,      cudaFuncAttributeMaxDynamicSharedMemorySize, GSM);
        cudaFuncSetAttribute(outproj_kernel, cudaFuncAttributeMaxDynamicSharedMemorySize, GSM);
        attr_done = true;
    }

    gn_kernel<<<Bn * 32, 256>>>(x, gw, gb);
    qkv_kernel<<<dim3(Nn / 128, Cc / 128, 12), 256, GSM>>>(Wq, bq, Wk, bk, Wv, bv);
    scores_kernel<<<dim3(Nn / 128, Nn / 128, Bn), 256, GSM>>>();
    softmax_kernel<<<Bn * Nn, 256>>>();
    ao_kernel<<<dim3(Nn / 128, Cc / 128, Bn), 256, GSM>>>();
    outproj_kernel<<<dim3(Nn / 128, Cc / 128, Bn), 256, GSM>>>(Wo, bo, x, out);
}

// round 9
// speedup vs baseline: 5.7338x; 1.0113x over previous
#include <cuda_runtime.h>
#include <cuda_fp16.h>
#include <cstdint>

#define Bn 4
#define Cc 256
#define Nn 4096
#define EPSf 1e-6f
#define RSQRT2f 0.70710678118654752440f
#define LOG2Ef 1.4426950408889634f
#define QSCALEf (0.0625f * LOG2Ef)

#define TP 144           // tile pitch bytes (64 halfs + 8 pad)
#define TILE_B 18432     // 128 * 144
#define GSM (4 * TILE_B) // A0,A1,B0,B1 dynamic smem

// Scratch (device globals — allocation-free contract).
__device__ __half g_hst[Bn * Nn * Cc];              // GN out, transposed [B][N][C]
__device__ __half g_wh [4 * Cc * Cc];               // Wq,Wk,Wv,Wo in fp16
__device__ __half g_qh [Bn * Nn * Cc];              // Q^T [B][N][C], pre-scaled
__device__ __half g_kh [Bn * Nn * Cc];              // K^T [B][N][C]
__device__ __half g_vh [Bn * Cc * Nn];              // V [B][C][N]
__device__ __half g_p  [(size_t)Bn * Nn * Nn];      // scores fp16 (log2-scaled)
__device__ __half g_ph [(size_t)Bn * Nn * Nn];      // probs fp16
__device__ __half g_aot[Bn * Nn * Cc];              // attn out transposed [B][N][C]

static __device__ __forceinline__ uint32_t smem_u32(const void* p) {
    uint32_t a;
    asm("{ .reg .u64 t; cvta.to.shared.u64 t, %1; cvt.u32.u64 %0, t; }" : "=r"(a) : "l"(p));
    return a;
}
#define LDSM4(r0, r1, r2, r3, addr)                                              \
    asm volatile("ldmatrix.sync.aligned.m8n8.x4.shared.b16 {%0,%1,%2,%3}, [%4];" \
                 : "=r"(r0), "=r"(r1), "=r"(r2), "=r"(r3) : "r"(addr))
#define MMA_F16(ac, a, b0, b1)                                                   \
    asm volatile("mma.sync.aligned.m16n8k16.row.col.f32.f16.f16.f32 "            \
                 "{%0,%1,%2,%3}, {%4,%5,%6,%7}, {%8,%9}, {%0,%1,%2,%3};"         \
                 : "+f"((ac)[0]), "+f"((ac)[1]), "+f"((ac)[2]), "+f"((ac)[3])    \
                 : "r"((a)[0]), "r"((a)[1]), "r"((a)[2]), "r"((a)[3]),           \
                   "r"(b0), "r"(b1))
#define CP_COMMIT() asm volatile("cp.async.commit_group;" ::: "memory")
#define CP_WAIT0()  asm volatile("cp.async.wait_group 0;" ::: "memory")

// cp.async a ROWSx64 fp16 tile (row-major src, stride STR halfs) into smem (pitch TP).
template <int ROWS, int STR, int NT>
static __device__ __forceinline__ void cp_tileN(uint32_t dst, const __half* src,
                                                int r0, int k0, int tid) {
    #pragma unroll
    for (int p = 0; p < ROWS * 8 / NT; p++) {
        int idx = tid + p * NT;
        int row = idx >> 3, seg = idx & 7;
        uint32_t d = dst + row * TP + seg * 16;
        const void* g = src + (size_t)(r0 + row) * STR + k0 + seg * 8;
        asm volatile("cp.async.ca.shared.global [%0], [%1], 16;" :: "r"(d), "l"(g));
    }
}

// 8-warp variant: 32(m) x 64(n) warp tile, one 64-wide K chunk.
static __device__ __forceinline__ void compute64(uint32_t aBase, uint32_t bBase,
                                                 int lane, int mW, int nW,
                                                 float acc[2][8][4]) {
    #pragma unroll
    for (int ks = 0; ks < 4; ks++) {
        const int kb = ks * 32 + ((lane >> 4) << 4);
        uint32_t a[2][4];
        #pragma unroll
        for (int ma = 0; ma < 2; ma++) {
            uint32_t ad = aBase + (mW + ma * 16 + (lane & 15)) * TP + kb;
            LDSM4(a[ma][0], a[ma][1], a[ma][2], a[ma][3], ad);
        }
        #pragma unroll
        for (int nb = 0; nb < 4; nb++) {
            uint32_t b0, b1, b2, b3;
            uint32_t bd = bBase + (nW + nb * 16 + (lane & 15)) * TP + kb;
            LDSM4(b0, b1, b2, b3, bd);
            #pragma unroll
            for (int ma = 0; ma < 2; ma++) {
                MMA_F16(acc[ma][nb * 2 + 0], a[ma], b0, b2);
                MMA_F16(acc[ma][nb * 2 + 1], a[ma], b1, b3);
            }
        }
    }
}

// 4-warp variant: 64(m) x 64(n) warp tile, one 64-wide K chunk.
static __device__ __forceinline__ void compute64x64(uint32_t aBase, uint32_t bBase,
                                                    int lane, int mW, int nW,
                                                    float acc[4][8][4]) {
    #pragma unroll
    for (int ks = 0; ks < 4; ks++) {
        const int kb = ks * 32 + ((lane >> 4) << 4);
        uint32_t a[4][4];
        #pragma unroll
        for (int ma = 0; ma < 4; ma++) {
            uint32_t ad = aBase + (mW + ma * 16 + (lane & 15)) * TP + kb;
            LDSM4(a[ma][0], a[ma][1], a[ma][2], a[ma][3], ad);
        }
        #pragma unroll
        for (int nb = 0; nb < 4; nb++) {
            uint32_t b0, b1, b2, b3;
            uint32_t bd = bBase + (nW + nb * 16 + (lane & 15)) * TP + kb;
            LDSM4(b0, b1, b2, b3, bd);
            #pragma unroll
            for (int ma = 0; ma < 4; ma++) {
                MMA_F16(acc[ma][nb * 2 + 0], a[ma], b0, b2);
                MMA_F16(acc[ma][nb * 2 + 1], a[ma], b1, b3);
            }
        }
    }
}

// ---------------- weight pre-convert: fp32 -> fp16 ----------------
__global__ void __launch_bounds__(256) cvtW_kernel(const float* __restrict__ Wq,
                                                   const float* __restrict__ Wk,
                                                   const float* __restrict__ Wv,
                                                   const float* __restrict__ Wo) {
    const float* s;
    switch (blockIdx.y) {
        case 0: s = Wq; break;
        case 1: s = Wk; break;
        case 2: s = Wv; break;
        default: s = Wo; break;
    }
    __half* d = g_wh + blockIdx.y * (Cc * Cc);
    int i = (blockIdx.x * 256 + threadIdx.x) * 4;
    float4 v = *(const float4*)(s + i);
    __half2 h0 = __floats2half2_rn(v.x, v.y);
    __half2 h1 = __floats2half2_rn(v.z, v.w);
    uint2 u = { *(uint32_t*)&h0, *(uint32_t*)&h1 };
    *(uint2*)(d + i) = u;
}

// ---------------- GroupNorm: x [B][C][N] fp32 -> g_hst [B][N][C] fp16 ----------------
__global__ void __launch_bounds__(256) gn_kernel(const float* __restrict__ x,
                                                 const float* __restrict__ w,
                                                 const float* __restrict__ bgn) {
    const int bb = blockIdx.x >> 5, g = blockIdx.x & 31;
    const int GSIZE = 8 * Nn;
    const size_t base = (size_t)(bb * Cc + g * 8) * Nn;
    const float* xp = x + base;
    float s = 0.f, s2 = 0.f;
    for (int i = threadIdx.x; i < GSIZE; i += 256) { float v = xp[i]; s += v; s2 += v * v; }
    __shared__ float r1[8], r2[8], shm, shr;
    #pragma unroll
    for (int o = 16; o; o >>= 1) {
        s += __shfl_xor_sync(~0u, s, o); s2 += __shfl_xor_sync(~0u, s2, o);
    }
    if ((threadIdx.x & 31) == 0) { r1[threadIdx.x >> 5] = s; r2[threadIdx.x >> 5] = s2; }
    __syncthreads();
    if (threadIdx.x == 0) {
        s = 0.f; s2 = 0.f;
        #pragma unroll
        for (int i = 0; i < 8; i++) { s += r1[i]; s2 += r2[i]; }
        float mean = s / GSIZE, var = s2 / GSIZE - mean * mean;
        shm = mean; shr = rsqrtf(var + EPSf);
    }
    __syncthreads();
    const float mean = shm, rstd = shr;
    float wl[8], bl[8];
    #pragma unroll
    for (int c = 0; c < 8; c++) { wl[c] = w[g * 8 + c] * rstd; bl[c] = bgn[g * 8 + c]; }
    __half* hp = g_hst + (size_t)bb * Nn * Cc + g * 8;
    for (int n = threadIdx.x; n < Nn; n += 256) {
        __half h[8];
        #pragma unroll
        for (int c = 0; c < 8; c++)
            h[c] = __float2half((xp[(size_t)c * Nn + n] - mean) * wl[c] + bl[c]);
        *(uint4*)(hp + (size_t)n * Cc) = *(uint4*)h;
    }
}

// ---------------- QKV: 8 warps, A = fp16 W (cp), B = hst (cp) ----------------
__global__ void __launch_bounds__(256, 2) qkv_kernel(const float* __restrict__ bq,
                                                     const float* __restrict__ bk,
                                                     const float* __restrict__ bv) {
    extern __shared__ char sm[];
    const int z = blockIdx.z, which = z >> 2, bb = z & 3;
    const float* bias = (which == 0) ? bq : (which == 1) ? bk : bv;
    const __half* A = g_wh + which * (Cc * Cc);
    const __half* Bm = g_hst + (size_t)bb * Nn * Cc;
    const int tid = threadIdx.x, lane = tid & 31, wid = tid >> 5;
    const int lr = lane >> 2, lc = lane & 3;
    const int mW = (wid & 3) * 32, nW = (wid >> 2) * 64;
    const int rowB = blockIdx.y * 128, colB = blockIdx.x * 128;
    float acc[2][8][4] = {};
    uint32_t sb = smem_u32(sm);
    uint32_t aB[2] = {sb, sb + TILE_B}, bB[2] = {sb + 2 * TILE_B, sb + 3 * TILE_B};

    cp_tileN<128, Cc, 256>(aB[0], A, rowB, 0, tid);
    cp_tileN<128, Cc, 256>(bB[0], Bm, colB, 0, tid);
    CP_COMMIT();
    #pragma unroll 1
    for (int c = 0; c < 4; c++) {
        CP_WAIT0();
        __syncthreads();
        if (c + 1 < 4) {
            cp_tileN<128, Cc, 256>(aB[(c + 1) & 1], A, rowB, (c + 1) * 64, tid);
            cp_tileN<128, Cc, 256>(bB[(c + 1) & 1], Bm, colB, (c + 1) * 64, tid);
            CP_COMMIT();
        }
        compute64(aB[c & 1], bB[c & 1], lane, mW, nW, acc);
    }
    const float fac = (which == 0) ? QSCALEf : 1.f;
    #pragma unroll
    for (int ma = 0; ma < 2; ma++) {
        int m0 = rowB + mW + ma * 16 + lr;
        float b0 = bias[m0], b1 = bias[m0 + 8];
        #pragma unroll
        for (int idx = 0; idx < 8; idx++) {
            int cI = colB + nW + (idx >> 1) * 16 + (idx & 1) * 8 + 2 * lc;
            if (which < 2) {
                __half* Cb = (which == 0 ? g_qh : g_kh) + (size_t)bb * Nn * Cc;
                Cb[(size_t)cI * Cc + m0]           = __float2half((acc[ma][idx][0] + b0) * fac);
                Cb[(size_t)(cI + 1) * Cc + m0]     = __float2half((acc[ma][idx][1] + b0) * fac);
                Cb[(size_t)cI * Cc + m0 + 8]       = __float2half((acc[ma][idx][2] + b1) * fac);
                Cb[(size_t)(cI + 1) * Cc + m0 + 8] = __float2half((acc[ma][idx][3] + b1) * fac);
            } else {
                __half* Cb = g_vh + (size_t)bb * Cc * Nn;
                __half2 p0 = __floats2half2_rn(acc[ma][idx][0] + b0, acc[ma][idx][1] + b0);
                __half2 p1 = __floats2half2_rn(acc[ma][idx][2] + b1, acc[ma][idx][3] + b1);
                *(__half2*)(Cb + (size_t)m0 * Nn + cI)       = p0;
                *(__half2*)(Cb + (size_t)(m0 + 8) * Nn + cI) = p1;
            }
        }
    }
}

// ---------------- scores: 4 warps of 64x64, S = Q'^T K -> fp16 ----------------
__global__ void __launch_bounds__(128, 2) scores_kernel() {
    extern __shared__ char sm[];
    const int tid = threadIdx.x, lane = tid & 31, wid = tid >> 5;
    const int lr = lane >> 2, lc = lane & 3;
    const int mW = (wid & 1) * 64, nW = (wid >> 1) * 64;
    const int bb = blockIdx.z, rowB = blockIdx.y * 128, colB = blockIdx.x * 128;
    const __half* Qt = g_qh + (size_t)bb * Nn * Cc;
    const __half* Kt = g_kh + (size_t)bb * Nn * Cc;
    __half* S = g_p + (size_t)bb * Nn * Nn;
    float acc[4][8][4] = {};
    uint32_t sb = smem_u32(sm);
    uint32_t aB[2] = {sb, sb + TILE_B}, bB[2] = {sb + 2 * TILE_B, sb + 3 * TILE_B};

    cp_tileN<128, Cc, 128>(aB[0], Qt, rowB, 0, tid);
    cp_tileN<128, Cc, 128>(bB[0], Kt, colB, 0, tid);
    CP_COMMIT();
    #pragma unroll 1
    for (int c = 0; c < 4; c++) {
        CP_WAIT0();
        __syncthreads();
        if (c + 1 < 4) {
            cp_tileN<128, Cc, 128>(aB[(c + 1) & 1], Qt, rowB, (c + 1) * 64, tid);
            cp_tileN<128, Cc, 128>(bB[(c + 1) & 1], Kt, colB, (c + 1) * 64, tid);
            CP_COMMIT();
        }
        compute64x64(aB[c & 1], bB[c & 1], lane, mW, nW, acc);
    }
    #pragma unroll
    for (int ma = 0; ma < 4; ma++) {
        int m0 = rowB + mW + ma * 16 + lr;
        #pragma unroll
        for (int idx = 0; idx < 8; idx++) {
            int cI = colB + nW + (idx >> 1) * 16 + (idx & 1) * 8 + 2 * lc;
            __half2 v0 = __floats2half2_rn(acc[ma][idx][0], acc[ma][idx][1]);
            __half2 v1 = __floats2half2_rn(acc[ma][idx][2], acc[ma][idx][3]);
            *(__half2*)(S + (size_t)m0 * Nn + cI)       = v0;
            *(__half2*)(S + (size_t)(m0 + 8) * Nn + cI) = v1;
        }
    }
}

// ---------------- softmax: S fp16 (log2-domain) -> P fp16 via ex2.f16x2 ----------------
__global__ void __launch_bounds__(256) softmax_kernel() {
    __shared__ __half2 buf[Nn / 2];
    __shared__ float red[8];
    const uint4* p = (const uint4*)(g_p + (size_t)blockIdx.x * Nn);
    uint4* pb = (uint4*)(g_ph + (size_t)blockIdx.x * Nn);
    const int tid = threadIdx.x;

    float m = -3.4e38f;
    #pragma unroll
    for (int it = 0; it < 2; it++) {
        int i = tid + it * 256;
        uint4 v = p[i];
        *(uint4*)(buf + i * 4) = v;
        __half2 h0 = *(__half2*)&v.x, h1 = *(__half2*)&v.y;
        __half2 h2 = *(__half2*)&v.z, h3 = *(__half2*)&v.w;
        __half2 mx = __hmax2(__hmax2(h0, h1), __hmax2(h2, h3));
        m = fmaxf(m, fmaxf(__low2float(mx), __high2float(mx)));
    }
    #pragma unroll
    for (int o = 16; o; o >>= 1) m = fmaxf(m, __shfl_xor_sync(~0u, m, o));
    if ((tid & 31) == 0) red[tid >> 5] = m;
    __syncthreads();
    if (tid < 8) {
        m = red[tid];
        #pragma unroll
        for (int o = 4; o; o >>= 1) m = fmaxf(m, __shfl_xor_sync(0xffu, m, o));
        if (tid == 0) red[0] = m;
    }
    __syncthreads();
    const __half2 m2 = __float2half2_rn(red[0]);
    __syncthreads();

    float sum = 0.f;
    #pragma unroll
    for (int it = 0; it < 8; it++) {
        int i = tid + it * 256;
        __half2 e = h2exp2(__hsub2(buf[i], m2));
        buf[i] = e;
        float2 f = __half22float2(e);
        sum += f.x + f.y;
    }
    #pragma unroll
    for (int o = 16; o; o >>= 1) sum += __shfl_xor_sync(~0u, sum, o);
    if ((tid & 31) == 0) red[tid >> 5] = sum;
    __syncthreads();
    if (tid < 8) {
        sum = red[tid];
        #pragma unroll
        for (int o = 4; o; o >>= 1) sum += __shfl_xor_sync(0xffu, sum, o);
        if (tid == 0) red[0] = sum;
    }
    __syncthreads();
    const __half2 inv = __float2half2_rn(1.f / red[0]);

    #pragma unroll
    for (int it = 0; it < 2; it++) {
        int i = tid + it * 256;
        __half2 e0 = __hmul2(buf[i * 4 + 0], inv);
        __half2 e1 = __hmul2(buf[i * 4 + 1], inv);
        __half2 e2 = __hmul2(buf[i * 4 + 2], inv);
        __half2 e3 = __hmul2(buf[i * 4 + 3], inv);
        uint4 v = { *(uint32_t*)&e0, *(uint32_t*)&e1, *(uint32_t*)&e2, *(uint32_t*)&e3 };
        pb[i] = v;
    }
}

// ---------------- ao: 4 warps of 64x64, AO[c][n] = sum_j V[c][j] P[n][j] ----------------
__global__ void __launch_bounds__(128, 2) ao_kernel() {
    extern __shared__ char sm[];
    const int tid = threadIdx.x, lane = tid & 31, wid = tid >> 5;
    const int lr = lane >> 2, lc = lane & 3;
    const int mW = (wid & 1) * 64, nW = (wid >> 1) * 64;
    const int bb = blockIdx.z, rowB = blockIdx.y * 128, colB = blockIdx.x * 128;
    const __half* Vh = g_vh + (size_t)bb * Cc * Nn;
    const __half* Ph = g_ph + (size_t)bb * Nn * Nn;
    __half* AOt = g_aot + (size_t)bb * Nn * Cc;
    float acc[4][8][4] = {};
    uint32_t sb = smem_u32(sm);
    uint32_t aB[2] = {sb, sb + TILE_B}, bB[2] = {sb + 2 * TILE_B, sb + 3 * TILE_B};

    cp_tileN<128, Nn, 128>(aB[0], Vh, rowB, 0, tid);
    cp_tileN<128, Nn, 128>(bB[0], Ph, colB, 0, tid);
    CP_COMMIT();
    #pragma unroll 1
    for (int c = 0; c < 64; c++) {
        CP_WAIT0();
        __syncthreads();
        if (c + 1 < 64) {
            cp_tileN<128, Nn, 128>(aB[(c + 1) & 1], Vh, rowB, (c + 1) * 64, tid);
            cp_tileN<128, Nn, 128>(bB[(c + 1) & 1], Ph, colB, (c + 1) * 64, tid);
            CP_COMMIT();
        }
        compute64x64(aB[c & 1], bB[c & 1], lane, mW, nW, acc);
    }
    #pragma unroll
    for (int ma = 0; ma < 4; ma++) {
        int m0 = rowB + mW + ma * 16 + lr;   // channel c
        #pragma unroll
        for (int idx = 0; idx < 8; idx++) {
            int cI = colB + nW + (idx >> 1) * 16 + (idx & 1) * 8 + 2 * lc;  // spatial n
            AOt[(size_t)cI * Cc + m0]           = __float2half(acc[ma][idx][0]);
            AOt[(size_t)(cI + 1) * Cc + m0]     = __float2half(acc[ma][idx][1]);
            AOt[(size_t)cI * Cc + m0 + 8]       = __float2half(acc[ma][idx][2]);
            AOt[(size_t)(cI + 1) * Cc + m0 + 8] = __float2half(acc[ma][idx][3]);
        }
    }
}

// ---------------- outproj: 8 warps, A = fp16 Wo (cp), B = AOt (cp), residual ----------------
__global__ void __launch_bounds__(256, 2) outproj_kernel(const float* __restrict__ bo,
                                                         const float* __restrict__ x,
                                                         float* __restrict__ out) {
    extern __shared__ char sm[];
    const int tid = threadIdx.x, lane = tid & 31, wid = tid >> 5;
    const int lr = lane >> 2, lc = lane & 3;
    const int mW = (wid & 3) * 32, nW = (wid >> 2) * 64;
    const int bb = blockIdx.z, rowB = blockIdx.y * 128, colB = blockIdx.x * 128;
    const __half* A = g_wh + 3 * (Cc * Cc);
    const __half* Bm = g_aot + (size_t)bb * Nn * Cc;
    float acc[2][8][4] = {};
    uint32_t sb = smem_u32(sm);
    uint32_t aB[2] = {sb, sb + TILE_B}, bB[2] = {sb + 2 * TILE_B, sb + 3 * TILE_B};

    cp_tileN<128, Cc, 256>(aB[0], A, rowB, 0, tid);
    cp_tileN<128, Cc, 256>(bB[0], Bm, colB, 0, tid);
    CP_COMMIT();
    #pragma unroll 1
    for (int c = 0; c < 4; c++) {
        CP_WAIT0();
        __syncthreads();
        if (c + 1 < 4) {
            cp_tileN<128, Cc, 256>(aB[(c + 1) & 1], A, rowB, (c + 1) * 64, tid);
            cp_tileN<128, Cc, 256>(bB[(c + 1) & 1], Bm, colB, (c + 1) * 64, tid);
            CP_COMMIT();
        }
        compute64(aB[c & 1], bB[c & 1], lane, mW, nW, acc);
    }
    #pragma unroll
    for (int ma = 0; ma < 2; ma++) {
        int m0 = rowB + mW + ma * 16 + lr;
        float b0 = bo[m0], b1 = bo[m0 + 8];
        #pragma unroll
        for (int idx = 0; idx < 8; idx++) {
            int cI = colB + nW + (idx >> 1) * 16 + (idx & 1) * 8 + 2 * lc;
            size_t i0 = (size_t)(bb * Cc + m0) * Nn + cI;
            size_t i1 = (size_t)(bb * Cc + m0 + 8) * Nn + cI;
            float2 x0 = *(const float2*)(x + i0), x1 = *(const float2*)(x + i1);
            float2 v0 = {(x0.x + acc[ma][idx][0] + b0) * RSQRT2f,
                         (x0.y + acc[ma][idx][1] + b0) * RSQRT2f};
            float2 v1 = {(x1.x + acc[ma][idx][2] + b1) * RSQRT2f,
                         (x1.y + acc[ma][idx][3] + b1) * RSQRT2f};
            *(float2*)(out + i0) = v0;
            *(float2*)(out + i1) = v1;
        }
    }
}

// ---------------------------------------------------------------------------
extern "C" void kernel_launch(void* const* d_in, const int* in_sizes, int n_in,
                              void* d_out, int out_size) {
    const float* x  = (const float*)d_in[0];
    const float* gw = (const float*)d_in[1];
    const float* gb = (const float*)d_in[2];
    const float* Wq = (const float*)d_in[3];
    const float* bq = (const float*)d_in[4];
    const float* Wk = (const float*)d_in[5];
    const float* bk = (const float*)d_in[6];
    const float* Wv = (const float*)d_in[7];
    const float* bv = (const float*)d_in[8];
    const float* Wo = (const float*)d_in[9];
    const float* bo = (const float*)d_in[10];
    float* out = (float*)d_out;

    cudaFuncSetAttribute(qkv_kernel,     cudaFuncAttributeMaxDynamicSharedMemorySize, GSM);
    cudaFuncSetAttribute(scores_kernel,  cudaFuncAttributeMaxDynamicSharedMemorySize, GSM);
    cudaFuncSetAttribute(ao_kernel,      cudaFuncAttributeMaxDynamicSharedMemorySize, GSM);
    cudaFuncSetAttribute(outproj_kernel, cudaFuncAttributeMaxDynamicSharedMemorySize, GSM);

    cvtW_kernel<<<dim3(64, 4), 256>>>(Wq, Wk, Wv, Wo);
    gn_kernel<<<Bn * 32, 256>>>(x, gw, gb);
    qkv_kernel<<<dim3(Nn / 128, Cc / 128, 12), 256, GSM>>>(bq, bk, bv);
    scores_kernel<<<dim3(Nn / 128, Nn / 128, Bn), 128, GSM>>>();
    softmax_kernel<<<Bn * Nn, 256>>>();
    ao_kernel<<<dim3(Nn / 128, Cc / 128, Bn), 128, GSM>>>();
    outproj_kernel<<<dim3(Nn / 128, Cc / 128, Bn), 256, GSM>>>(bo, x, out);
}

// round 10
// speedup vs baseline: 5.7662x; 1.0056x over previous
#include <cuda_runtime.h>
#include <cuda_fp16.h>
#include <cstdint>

#define Bn 4
#define Cc 256
#define Nn 4096
#define EPSf 1e-6f
#define RSQRT2f 0.70710678118654752440f
#define LOG2Ef 1.4426950408889634f
#define QSCALEf (0.0625f * LOG2Ef)

#define TP 144           // tile pitch bytes (64 halfs + 8 pad)
#define TILE_B 18432     // 128 * 144
#define GSM (4 * TILE_B) // A0,A1,B0,B1 dynamic smem

// Scratch (device globals — allocation-free contract).
__device__ __half g_hst[Bn * Nn * Cc];              // GN out, transposed [B][N][C]
__device__ __half g_wh [4 * Cc * Cc];               // Wq,Wk,Wv,Wo in fp16
__device__ __half g_qh [Bn * Nn * Cc];              // Q^T [B][N][C], pre-scaled
__device__ __half g_kh [Bn * Nn * Cc];              // K^T [B][N][C]
__device__ __half g_vh [Bn * Cc * Nn];              // V [B][C][N]
__device__ __half g_p  [(size_t)Bn * Nn * Nn];      // scores fp16 (log2-scaled)
__device__ __half g_ph [(size_t)Bn * Nn * Nn];      // probs fp16
__device__ __half g_aot[Bn * Nn * Cc];              // attn out transposed [B][N][C]

static __device__ __forceinline__ uint32_t smem_u32(const void* p) {
    uint32_t a;
    asm("{ .reg .u64 t; cvta.to.shared.u64 t, %1; cvt.u32.u64 %0, t; }" : "=r"(a) : "l"(p));
    return a;
}
#define LDSM4(r0, r1, r2, r3, addr)                                              \
    asm volatile("ldmatrix.sync.aligned.m8n8.x4.shared.b16 {%0,%1,%2,%3}, [%4];" \
                 : "=r"(r0), "=r"(r1), "=r"(r2), "=r"(r3) : "r"(addr))
#define MMA_F16(ac, a, b0, b1)                                                   \
    asm volatile("mma.sync.aligned.m16n8k16.row.col.f32.f16.f16.f32 "            \
                 "{%0,%1,%2,%3}, {%4,%5,%6,%7}, {%8,%9}, {%0,%1,%2,%3};"         \
                 : "+f"((ac)[0]), "+f"((ac)[1]), "+f"((ac)[2]), "+f"((ac)[3])    \
                 : "r"((a)[0]), "r"((a)[1]), "r"((a)[2]), "r"((a)[3]),           \
                   "r"(b0), "r"(b1))
#define CP_COMMIT() asm volatile("cp.async.commit_group;" ::: "memory")
#define CP_WAIT0()  asm volatile("cp.async.wait_group 0;" ::: "memory")

// cp.async a 128x64 fp16 tile (row-major src, stride STR halfs) into smem (pitch TP).
template <int STR>
static __device__ __forceinline__ void cp_tile(uint32_t dst, const __half* src,
                                               int r0, int k0, int tid) {
    #pragma unroll
    for (int p = 0; p < 4; p++) {
        int idx = tid + p * 256;
        int row = idx >> 3, seg = idx & 7;
        uint32_t d = dst + row * TP + seg * 16;
        const void* g = src + (size_t)(r0 + row) * STR + k0 + seg * 8;
        asm volatile("cp.async.ca.shared.global [%0], [%1], 16;" :: "r"(d), "l"(g));
    }
}

// One 64-wide K chunk of fp16 mma for a 32(m) x 64(n) warp tile (8 warps/CTA).
static __device__ __forceinline__ void compute64(uint32_t aBase, uint32_t bBase,
                                                 int lane, int mW, int nW,
                                                 float acc[2][8][4]) {
    #pragma unroll
    for (int ks = 0; ks < 4; ks++) {
        const int kb = ks * 32 + ((lane >> 4) << 4);
        uint32_t a[2][4];
        #pragma unroll
        for (int ma = 0; ma < 2; ma++) {
            uint32_t ad = aBase + (mW + ma * 16 + (lane & 15)) * TP + kb;
            LDSM4(a[ma][0], a[ma][1], a[ma][2], a[ma][3], ad);
        }
        #pragma unroll
        for (int nb = 0; nb < 4; nb++) {
            uint32_t b0, b1, b2, b3;
            uint32_t bd = bBase + (nW + nb * 16 + (lane & 15)) * TP + kb;
            LDSM4(b0, b1, b2, b3, bd);
            #pragma unroll
            for (int ma = 0; ma < 2; ma++) {
                MMA_F16(acc[ma][nb * 2 + 0], a[ma], b0, b2);
                MMA_F16(acc[ma][nb * 2 + 1], a[ma], b1, b3);
            }
        }
    }
}

// ---------------- weight pre-convert: fp32 -> fp16 ----------------
__global__ void __launch_bounds__(256) cvtW_kernel(const float* __restrict__ Wq,
                                                   const float* __restrict__ Wk,
                                                   const float* __restrict__ Wv,
                                                   const float* __restrict__ Wo) {
    const float* s;
    switch (blockIdx.y) {
        case 0: s = Wq; break;
        case 1: s = Wk; break;
        case 2: s = Wv; break;
        default: s = Wo; break;
    }
    __half* d = g_wh + blockIdx.y * (Cc * Cc);
    int i = (blockIdx.x * 256 + threadIdx.x) * 4;
    float4 v = *(const float4*)(s + i);
    __half2 h0 = __floats2half2_rn(v.x, v.y);
    __half2 h1 = __floats2half2_rn(v.z, v.w);
    uint2 u = { *(uint32_t*)&h0, *(uint32_t*)&h1 };
    *(uint2*)(d + i) = u;
}

// ---------------- GroupNorm: x [B][C][N] fp32 -> g_hst [B][N][C] fp16 ----------------
__global__ void __launch_bounds__(256) gn_kernel(const float* __restrict__ x,
                                                 const float* __restrict__ w,
                                                 const float* __restrict__ bgn) {
    const int bb = blockIdx.x >> 5, g = blockIdx.x & 31;
    const int GSIZE = 8 * Nn;
    const size_t base = (size_t)(bb * Cc + g * 8) * Nn;
    const float* xp = x + base;
    float s = 0.f, s2 = 0.f;
    for (int i = threadIdx.x; i < GSIZE; i += 256) { float v = xp[i]; s += v; s2 += v * v; }
    __shared__ float r1[8], r2[8], shm, shr;
    #pragma unroll
    for (int o = 16; o; o >>= 1) {
        s += __shfl_xor_sync(~0u, s, o); s2 += __shfl_xor_sync(~0u, s2, o);
    }
    if ((threadIdx.x & 31) == 0) { r1[threadIdx.x >> 5] = s; r2[threadIdx.x >> 5] = s2; }
    __syncthreads();
    if (threadIdx.x == 0) {
        s = 0.f; s2 = 0.f;
        #pragma unroll
        for (int i = 0; i < 8; i++) { s += r1[i]; s2 += r2[i]; }
        float mean = s / GSIZE, var = s2 / GSIZE - mean * mean;
        shm = mean; shr = rsqrtf(var + EPSf);
    }
    __syncthreads();
    const float mean = shm, rstd = shr;
    float wl[8], bl[8];
    #pragma unroll
    for (int c = 0; c < 8; c++) { wl[c] = w[g * 8 + c] * rstd; bl[c] = bgn[g * 8 + c]; }
    __half* hp = g_hst + (size_t)bb * Nn * Cc + g * 8;
    for (int n = threadIdx.x; n < Nn; n += 256) {
        __half h[8];
        #pragma unroll
        for (int c = 0; c < 8; c++)
            h[c] = __float2half((xp[(size_t)c * Nn + n] - mean) * wl[c] + bl[c]);
        *(uint4*)(hp + (size_t)n * Cc) = *(uint4*)h;
    }
}

// ---------------- QKV: 8 warps, A = fp16 W (cp), B = hst (cp) ----------------
__global__ void __launch_bounds__(256, 2) qkv_kernel(const float* __restrict__ bq,
                                                     const float* __restrict__ bk,
                                                     const float* __restrict__ bv) {
    extern __shared__ char sm[];
    const int z = blockIdx.z, which = z >> 2, bb = z & 3;
    const float* bias = (which == 0) ? bq : (which == 1) ? bk : bv;
    const __half* A = g_wh + which * (Cc * Cc);
    const __half* Bm = g_hst + (size_t)bb * Nn * Cc;
    const int tid = threadIdx.x, lane = tid & 31, wid = tid >> 5;
    const int lr = lane >> 2, lc = lane & 3;
    const int mW = (wid & 3) * 32, nW = (wid >> 2) * 64;
    const int rowB = blockIdx.y * 128, colB = blockIdx.x * 128;
    float acc[2][8][4] = {};
    uint32_t sb = smem_u32(sm);
    uint32_t aB[2] = {sb, sb + TILE_B}, bB[2] = {sb + 2 * TILE_B, sb + 3 * TILE_B};

    cp_tile<Cc>(aB[0], A, rowB, 0, tid);
    cp_tile<Cc>(bB[0], Bm, colB, 0, tid);
    CP_COMMIT();
    #pragma unroll 1
    for (int c = 0; c < 4; c++) {
        CP_WAIT0();
        __syncthreads();
        if (c + 1 < 4) {
            cp_tile<Cc>(aB[(c + 1) & 1], A, rowB, (c + 1) * 64, tid);
            cp_tile<Cc>(bB[(c + 1) & 1], Bm, colB, (c + 1) * 64, tid);
            CP_COMMIT();
        }
        compute64(aB[c & 1], bB[c & 1], lane, mW, nW, acc);
    }
    const float fac = (which == 0) ? QSCALEf : 1.f;
    #pragma unroll
    for (int ma = 0; ma < 2; ma++) {
        int m0 = rowB + mW + ma * 16 + lr;
        float b0 = bias[m0], b1 = bias[m0 + 8];
        #pragma unroll
        for (int idx = 0; idx < 8; idx++) {
            int cI = colB + nW + (idx >> 1) * 16 + (idx & 1) * 8 + 2 * lc;
            if (which < 2) {
                __half* Cb = (which == 0 ? g_qh : g_kh) + (size_t)bb * Nn * Cc;
                Cb[(size_t)cI * Cc + m0]           = __float2half((acc[ma][idx][0] + b0) * fac);
                Cb[(size_t)(cI + 1) * Cc + m0]     = __float2half((acc[ma][idx][1] + b0) * fac);
                Cb[(size_t)cI * Cc + m0 + 8]       = __float2half((acc[ma][idx][2] + b1) * fac);
                Cb[(size_t)(cI + 1) * Cc + m0 + 8] = __float2half((acc[ma][idx][3] + b1) * fac);
            } else {
                __half* Cb = g_vh + (size_t)bb * Cc * Nn;
                __half2 p0 = __floats2half2_rn(acc[ma][idx][0] + b0, acc[ma][idx][1] + b0);
                __half2 p1 = __floats2half2_rn(acc[ma][idx][2] + b1, acc[ma][idx][3] + b1);
                *(__half2*)(Cb + (size_t)m0 * Nn + cI)       = p0;
                *(__half2*)(Cb + (size_t)(m0 + 8) * Nn + cI) = p1;
            }
        }
    }
}

// ---------------- scores: 8 warps of 32x64, S = Q'^T K -> fp16 ----------------
__global__ void __launch_bounds__(256, 2) scores_kernel() {
    extern __shared__ char sm[];
    const int tid = threadIdx.x, lane = tid & 31, wid = tid >> 5;
    const int lr = lane >> 2, lc = lane & 3;
    const int mW = (wid & 3) * 32, nW = (wid >> 2) * 64;
    const int bb = blockIdx.z, rowB = blockIdx.y * 128, colB = blockIdx.x * 128;
    const __half* Qt = g_qh + (size_t)bb * Nn * Cc;
    const __half* Kt = g_kh + (size_t)bb * Nn * Cc;
    __half* S = g_p + (size_t)bb * Nn * Nn;
    float acc[2][8][4] = {};
    uint32_t sb = smem_u32(sm);
    uint32_t aB[2] = {sb, sb + TILE_B}, bB[2] = {sb + 2 * TILE_B, sb + 3 * TILE_B};

    cp_tile<Cc>(aB[0], Qt, rowB, 0, tid);
    cp_tile<Cc>(bB[0], Kt, colB, 0, tid);
    CP_COMMIT();
    #pragma unroll 1
    for (int c = 0; c < 4; c++) {
        CP_WAIT0();
        __syncthreads();
        if (c + 1 < 4) {
            cp_tile<Cc>(aB[(c + 1) & 1], Qt, rowB, (c + 1) * 64, tid);
            cp_tile<Cc>(bB[(c + 1) & 1], Kt, colB, (c + 1) * 64, tid);
            CP_COMMIT();
        }
        compute64(aB[c & 1], bB[c & 1], lane, mW, nW, acc);
    }
    #pragma unroll
    for (int ma = 0; ma < 2; ma++) {
        int m0 = rowB + mW + ma * 16 + lr;
        #pragma unroll
        for (int idx = 0; idx < 8; idx++) {
            int cI = colB + nW + (idx >> 1) * 16 + (idx & 1) * 8 + 2 * lc;
            __half2 v0 = __floats2half2_rn(acc[ma][idx][0], acc[ma][idx][1]);
            __half2 v1 = __floats2half2_rn(acc[ma][idx][2], acc[ma][idx][3]);
            *(__half2*)(S + (size_t)m0 * Nn + cI)       = v0;
            *(__half2*)(S + (size_t)(m0 + 8) * Nn + cI) = v1;
        }
    }
}

// ---------------- softmax: S fp16 (log2-domain) -> P fp16 via ex2.f16x2 ----------------
__global__ void __launch_bounds__(256) softmax_kernel() {
    __shared__ __half2 buf[Nn / 2];
    __shared__ float red[8];
    const uint4* p = (const uint4*)(g_p + (size_t)blockIdx.x * Nn);
    uint4* pb = (uint4*)(g_ph + (size_t)blockIdx.x * Nn);
    const int tid = threadIdx.x;

    float m = -3.4e38f;
    #pragma unroll
    for (int it = 0; it < 2; it++) {
        int i = tid + it * 256;
        uint4 v = p[i];
        *(uint4*)(buf + i * 4) = v;
        __half2 h0 = *(__half2*)&v.x, h1 = *(__half2*)&v.y;
        __half2 h2 = *(__half2*)&v.z, h3 = *(__half2*)&v.w;
        __half2 mx = __hmax2(__hmax2(h0, h1), __hmax2(h2, h3));
        m = fmaxf(m, fmaxf(__low2float(mx), __high2float(mx)));
    }
    #pragma unroll
    for (int o = 16; o; o >>= 1) m = fmaxf(m, __shfl_xor_sync(~0u, m, o));
    if ((tid & 31) == 0) red[tid >> 5] = m;
    __syncthreads();
    if (tid < 8) {
        m = red[tid];
        #pragma unroll
        for (int o = 4; o; o >>= 1) m = fmaxf(m, __shfl_xor_sync(0xffu, m, o));
        if (tid == 0) red[0] = m;
    }
    __syncthreads();
    const __half2 m2 = __float2half2_rn(red[0]);
    __syncthreads();

    float sum = 0.f;
    #pragma unroll
    for (int it = 0; it < 8; it++) {
        int i = tid + it * 256;
        __half2 e = h2exp2(__hsub2(buf[i], m2));
        buf[i] = e;
        float2 f = __half22float2(e);
        sum += f.x + f.y;
    }
    #pragma unroll
    for (int o = 16; o; o >>= 1) sum += __shfl_xor_sync(~0u, sum, o);
    if ((tid & 31) == 0) red[tid >> 5] = sum;
    __syncthreads();
    if (tid < 8) {
        sum = red[tid];
        #pragma unroll
        for (int o = 4; o; o >>= 1) sum += __shfl_xor_sync(0xffu, sum, o);
        if (tid == 0) red[0] = sum;
    }
    __syncthreads();
    const __half2 inv = __float2half2_rn(1.f / red[0]);

    #pragma unroll
    for (int it = 0; it < 2; it++) {
        int i = tid + it * 256;
        __half2 e0 = __hmul2(buf[i * 4 + 0], inv);
        __half2 e1 = __hmul2(buf[i * 4 + 1], inv);
        __half2 e2 = __hmul2(buf[i * 4 + 2], inv);
        __half2 e3 = __hmul2(buf[i * 4 + 3], inv);
        uint4 v = { *(uint32_t*)&e0, *(uint32_t*)&e1, *(uint32_t*)&e2, *(uint32_t*)&e3 };
        pb[i] = v;
    }
}

// ---------------- ao: 8 warps of 32x64, AO[c][n] = sum_j V[c][j] P[n][j] ----------------
__global__ void __launch_bounds__(256, 2) ao_kernel() {
    extern __shared__ char sm[];
    const int tid = threadIdx.x, lane = tid & 31, wid = tid >> 5;
    const int lr = lane >> 2, lc = lane & 3;
    const int mW = (wid & 3) * 32, nW = (wid >> 2) * 64;
    const int bb = blockIdx.z, rowB = blockIdx.y * 128, colB = blockIdx.x * 128;
    const __half* Vh = g_vh + (size_t)bb * Cc * Nn;
    const __half* Ph = g_ph + (size_t)bb * Nn * Nn;
    __half* AOt = g_aot + (size_t)bb * Nn * Cc;
    float acc[2][8][4] = {};
    uint32_t sb = smem_u32(sm);
    uint32_t aB[2] = {sb, sb + TILE_B}, bB[2] = {sb + 2 * TILE_B, sb + 3 * TILE_B};

    cp_tile<Nn>(aB[0], Vh, rowB, 0, tid);
    cp_tile<Nn>(bB[0], Ph, colB, 0, tid);
    CP_COMMIT();
    #pragma unroll 1
    for (int c = 0; c < 64; c++) {
        CP_WAIT0();
        __syncthreads();
        if (c + 1 < 64) {
            cp_tile<Nn>(aB[(c + 1) & 1], Vh, rowB, (c + 1) * 64, tid);
            cp_tile<Nn>(bB[(c + 1) & 1], Ph, colB, (c + 1) * 64, tid);
            CP_COMMIT();
        }
        compute64(aB[c & 1], bB[c & 1], lane, mW, nW, acc);
    }
    #pragma unroll
    for (int ma = 0; ma < 2; ma++) {
        int m0 = rowB + mW + ma * 16 + lr;   // channel c
        #pragma unroll
        for (int idx = 0; idx < 8; idx++) {
            int cI = colB + nW + (idx >> 1) * 16 + (idx & 1) * 8 + 2 * lc;  // spatial n
            AOt[(size_t)cI * Cc + m0]           = __float2half(acc[ma][idx][0]);
            AOt[(size_t)(cI + 1) * Cc + m0]     = __float2half(acc[ma][idx][1]);
            AOt[(size_t)cI * Cc + m0 + 8]       = __float2half(acc[ma][idx][2]);
            AOt[(size_t)(cI + 1) * Cc + m0 + 8] = __float2half(acc[ma][idx][3]);
        }
    }
}

// ---------------- outproj: 8 warps, A = fp16 Wo (cp), B = AOt (cp), residual ----------------
__global__ void __launch_bounds__(256, 2) outproj_kernel(const float* __restrict__ bo,
                                                         const float* __restrict__ x,
                                                         float* __restrict__ out) {
    extern __shared__ char sm[];
    const int tid = threadIdx.x, lane = tid & 31, wid = tid >> 5;
    const int lr = lane >> 2, lc = lane & 3;
    const int mW = (wid & 3) * 32, nW = (wid >> 2) * 64;
    const int bb = blockIdx.z, rowB = blockIdx.y * 128, colB = blockIdx.x * 128;
    const __half* A = g_wh + 3 * (Cc * Cc);
    const __half* Bm = g_aot + (size_t)bb * Nn * Cc;
    float acc[2][8][4] = {};
    uint32_t sb = smem_u32(sm);
    uint32_t aB[2] = {sb, sb + TILE_B}, bB[2] = {sb + 2 * TILE_B, sb + 3 * TILE_B};

    cp_tile<Cc>(aB[0], A, rowB, 0, tid);
    cp_tile<Cc>(bB[0], Bm, colB, 0, tid);
    CP_COMMIT();
    #pragma unroll 1
    for (int c = 0; c < 4; c++) {
        CP_WAIT0();
        __syncthreads();
        if (c + 1 < 4) {
            cp_tile<Cc>(aB[(c + 1) & 1], A, rowB, (c + 1) * 64, tid);
            cp_tile<Cc>(bB[(c + 1) & 1], Bm, colB, (c + 1) * 64, tid);
            CP_COMMIT();
        }
        compute64(aB[c & 1], bB[c & 1], lane, mW, nW, acc);
    }
    #pragma unroll
    for (int ma = 0; ma < 2; ma++) {
        int m0 = rowB + mW + ma * 16 + lr;
        float b0 = bo[m0], b1 = bo[m0 + 8];
        #pragma unroll
        for (int idx = 0; idx < 8; idx++) {
            int cI = colB + nW + (idx >> 1) * 16 + (idx & 1) * 8 + 2 * lc;
            size_t i0 = (size_t)(bb * Cc + m0) * Nn + cI;
            size_t i1 = (size_t)(bb * Cc + m0 + 8) * Nn + cI;
            float2 x0 = *(const float2*)(x + i0), x1 = *(const float2*)(x + i1);
            float2 v0 = {(x0.x + acc[ma][idx][0] + b0) * RSQRT2f,
                         (x0.y + acc[ma][idx][1] + b0) * RSQRT2f};
            float2 v1 = {(x1.x + acc[ma][idx][2] + b1) * RSQRT2f,
                         (x1.y + acc[ma][idx][3] + b1) * RSQRT2f};
            *(float2*)(out + i0) = v0;
            *(float2*)(out + i1) = v1;
        }
    }
}

// ---------------------------------------------------------------------------
extern "C" void kernel_launch(void* const* d_in, const int* in_sizes, int n_in,
                              void* d_out, int out_size) {
    const float* x  = (const float*)d_in[0];
    const float* gw = (const float*)d_in[1];
    const float* gb = (const float*)d_in[2];
    const float* Wq = (const float*)d_in[3];
    const float* bq = (const float*)d_in[4];
    const float* Wk = (const float*)d_in[5];
    const float* bk = (const float*)d_in[6];
    const float* Wv = (const float*)d_in[7];
    const float* bv = (const float*)d_in[8];
    const float* Wo = (const float*)d_in[9];
    const float* bo = (const float*)d_in[10];
    float* out = (float*)d_out;

    cudaFuncSetAttribute(qkv_kernel,     cudaFuncAttributeMaxDynamicSharedMemorySize, GSM);
    cudaFuncSetAttribute(scores_kernel,  cudaFuncAttributeMaxDynamicSharedMemorySize, GSM);
    cudaFuncSetAttribute(ao_kernel,      cudaFuncAttributeMaxDynamicSharedMemorySize, GSM);
    cudaFuncSetAttribute(outproj_kernel, cudaFuncAttributeMaxDynamicSharedMemorySize, GSM);

    cvtW_kernel<<<dim3(64, 4), 256>>>(Wq, Wk, Wv, Wo);
    gn_kernel<<<Bn * 32, 256>>>(x, gw, gb);
    qkv_kernel<<<dim3(Nn / 128, Cc / 128, 12), 256, GSM>>>(bq, bk, bv);
    scores_kernel<<<dim3(Nn / 128, Nn / 128, Bn), 256, GSM>>>();
    softmax_kernel<<<Bn * Nn, 256>>>();
    ao_kernel<<<dim3(Nn / 128, Cc / 128, Bn), 256, GSM>>>();
    outproj_kernel<<<dim3(Nn / 128, Cc / 128, Bn), 256, GSM>>>(bo, x, out);
}